// round 9
// baseline (speedup 1.0000x reference)
#include <cuda_runtime.h>
#include <cuda_fp16.h>
#include <math.h>
#include <stdint.h>

// ---------------------------------------------------------------------------
// Problem constants
// ---------------------------------------------------------------------------
#define Bc    2
#define Sc    2048
#define HIDc  4096
#define Hc    32
#define KVc   8
#define Dc    128
#define Wc    512
#define BSc   (Bc * Sc)              // 4096
#define QKVF  ((Hc + 2 * KVc) * Dc)  // 6144

// global operand scale 2^10 (keeps fp16 residuals out of subnormal range)
#define SCF      1024.0f
#define INV_SC2  (1.0f / (SCF * SCF))

// ---------------------------------------------------------------------------
// Scratch (static device globals -- no allocation allowed)
// ---------------------------------------------------------------------------
__device__ float g_qkv[(size_t)BSc * QKVF];

__device__ __half g_qh[(size_t)BSc * Hc * Dc];
__device__ __half g_ql[(size_t)BSc * Hc * Dc];
__device__ __half g_kh[(size_t)BSc * KVc * Dc];
__device__ __half g_vth[(size_t)Bc * KVc * Dc * Sc];    // V^T [b][kv][d][s]

__device__ __half g_ah[(size_t)BSc * HIDc];
__device__ __half g_al[(size_t)BSc * HIDc];
__device__ __half g_bh[(size_t)QKVF * HIDc];

// ---------------------------------------------------------------------------
// Helpers
// ---------------------------------------------------------------------------
__device__ __forceinline__ uint32_t smem_u32(const void* p) {
    uint32_t a;
    asm("{ .reg .u64 t; cvta.to.shared.u64 t, %1; cvt.u32.u64 %0, t; }"
        : "=r"(a) : "l"(p));
    return a;
}
__device__ __forceinline__ void cp16(uint32_t smem, const void* gmem) {
    asm volatile("cp.async.cg.shared.global [%0], [%1], 16;"
                 :: "r"(smem), "l"(gmem));
}
#define CP_COMMIT() asm volatile("cp.async.commit_group;" ::: "memory")
#define CP_WAIT0()  asm volatile("cp.async.wait_group 0;" ::: "memory")
#define CP_WAIT1()  asm volatile("cp.async.wait_group 1;" ::: "memory")

__device__ __forceinline__ void ldsm_x4(uint32_t* r, uint32_t addr) {
    asm volatile("ldmatrix.sync.aligned.m8n8.x4.shared.b16 {%0,%1,%2,%3}, [%4];"
                 : "=r"(r[0]), "=r"(r[1]), "=r"(r[2]), "=r"(r[3]) : "r"(addr));
}

// fp16 HMMA m16n8k16, fp32 accumulate
__device__ __forceinline__ void mma16816(float* d, const uint32_t* a,
                                         const uint32_t* b) {
    asm volatile(
        "mma.sync.aligned.m16n8k16.row.col.f32.f16.f16.f32 "
        "{%0,%1,%2,%3}, {%4,%5,%6,%7}, {%8,%9}, {%0,%1,%2,%3};"
        : "+f"(d[0]), "+f"(d[1]), "+f"(d[2]), "+f"(d[3])
        : "r"(a[0]), "r"(a[1]), "r"(a[2]), "r"(a[3]),
          "r"(b[0]), "r"(b[1]));
}

__device__ __forceinline__ uint32_t packh_hi2(float x, float y) {
    __half2 h(__float2half_rn(x), __float2half_rn(y));
    return *(uint32_t*)&h;
}
__device__ __forceinline__ uint32_t packh_lo2(float x, float y) {
    float hx = __half2float(__float2half_rn(x));
    float hy = __half2float(__float2half_rn(y));
    __half2 l(__float2half_rn(x - hx), __float2half_rn(y - hy));
    return *(uint32_t*)&l;
}

// ---------------------------------------------------------------------------
// 2-term fp16 HMMA GEMM with 3-stage cp.async pipeline. 2 CTAs/SM.
// ---------------------------------------------------------------------------
#define GBK   32
#define SROW  40
#define MATB  (128 * SROW * 2)              // 10240 B
#define STAGEB (3 * MATB)                   // 30720 B (Ah, Al, Bh)
#define GEMM_SMEM (3 * STAGEB)              // 92160 B (3 stages)

__global__ __launch_bounds__(256, 2)
void gemm_mma(const __half* __restrict__ Ah,
              const __half* __restrict__ Al,
              const __half* __restrict__ Bh,
              float* __restrict__ C, int M, int N, int K)
{
    extern __shared__ char sm[];
    const uint32_t sb = smem_u32(sm);
    const int tid  = threadIdx.x;
    const int wid  = tid >> 5;
    const int lane = tid & 31;
    const int wm = wid & 3;
    const int wn = wid >> 2;
    const int g  = lane >> 2;
    const int tg = lane & 3;

    const int m0 = blockIdx.y * 128;
    const int n0 = blockIdx.x * 128;

    const uint32_t amrow = (lane & 7) + ((lane >> 3) & 1) * 8;
    const uint32_t acol  = (uint32_t)(lane >> 4) * 16;
    const uint32_t bmrow = (lane & 7) + (uint32_t)(lane >> 4) * 8;
    const uint32_t bcol  = ((lane >> 3) & 1) * 16;

    auto load_stage = [&](int k0, int st) {
        const uint32_t base = sb + st * STAGEB;
#pragma unroll
        for (int mat = 0; mat < 3; mat++) {
            const __half* src = (mat == 0) ? Ah : (mat == 1) ? Al : Bh;
            const int row0 = (mat < 2) ? m0 : n0;
#pragma unroll
            for (int hh = 0; hh < 2; hh++) {
                int unit = tid + hh * 256;
                int r = unit >> 2, u = unit & 3;
                const void* gp = src + (size_t)(row0 + r) * K + k0 + u * 8;
                cp16(base + mat * MATB + r * (SROW * 2) + u * 16, gp);
            }
        }
    };

    float acc[2][8][4];
#pragma unroll
    for (int mt = 0; mt < 2; mt++)
#pragma unroll
        for (int nt = 0; nt < 8; nt++)
#pragma unroll
            for (int j = 0; j < 4; j++) acc[mt][nt][j] = 0.f;

    const int NIT = K / GBK;
    load_stage(0, 0);
    CP_COMMIT();
    load_stage(GBK, 1);
    CP_COMMIT();

    int stc = 0;                 // compute stage index mod 3
    for (int it = 0; it < NIT; it++) {
        if (it + 1 < NIT) { CP_WAIT1(); } else { CP_WAIT0(); }
        __syncthreads();
        if (it + 2 < NIT) {
            int stn = stc + 2; if (stn >= 3) stn -= 3;
            load_stage((it + 2) * GBK, stn);
            CP_COMMIT();
        }

        const uint32_t ahb = sb + stc * STAGEB;
        const uint32_t bhb = ahb + 2 * MATB;

#pragma unroll
        for (int ks = 0; ks < 2; ks++) {
            uint32_t ah[2][4], al[2][4];
#pragma unroll
            for (int mt = 0; mt < 2; mt++) {
                const uint32_t ar = ahb +
                    (uint32_t)((wm * 32 + mt * 16 + amrow) * (SROW * 2)) +
                    (uint32_t)(ks * 32) + acol;
                ldsm_x4(ah[mt], ar);
                ldsm_x4(al[mt], ar + MATB);
            }
#pragma unroll
            for (int ntp = 0; ntp < 4; ntp++) {
                const uint32_t br = bhb +
                    (uint32_t)((wn * 64 + ntp * 16 + bmrow) * (SROW * 2)) +
                    (uint32_t)(ks * 32) + bcol;
                uint32_t bh4[4];
                ldsm_x4(bh4, br);
#pragma unroll
                for (int mt = 0; mt < 2; mt++) {
                    mma16816(acc[mt][2 * ntp],     ah[mt], &bh4[0]);
                    mma16816(acc[mt][2 * ntp],     al[mt], &bh4[0]);
                    mma16816(acc[mt][2 * ntp + 1], ah[mt], &bh4[2]);
                    mma16816(acc[mt][2 * ntp + 1], al[mt], &bh4[2]);
                }
            }
        }
        if (++stc == 3) stc = 0;
    }

#pragma unroll
    for (int mt = 0; mt < 2; mt++) {
        const int r0 = m0 + wm * 32 + mt * 16 + g;
#pragma unroll
        for (int nt = 0; nt < 8; nt++) {
            const int cc = n0 + wn * 64 + nt * 8 + tg * 2;
            float2 w0 = make_float2(acc[mt][nt][0] * INV_SC2,
                                    acc[mt][nt][1] * INV_SC2);
            float2 w1 = make_float2(acc[mt][nt][2] * INV_SC2,
                                    acc[mt][nt][3] * INV_SC2);
            *(float2*)(C + (size_t)r0 * N + cc)       = w0;
            *(float2*)(C + (size_t)(r0 + 8) * N + cc) = w1;
        }
    }
}

// ---------------------------------------------------------------------------
// Split fp32 -> scaled fp16 (hi, lo)
// ---------------------------------------------------------------------------
__global__ void split_a_kernel(const float* __restrict__ X,
                               __half* __restrict__ Xh,
                               __half* __restrict__ Xl, int n4)
{
    int i = blockIdx.x * blockDim.x + threadIdx.x;
    if (i >= n4) return;
    float4 v = ((const float4*)X)[i];
    v.x *= SCF; v.y *= SCF; v.z *= SCF; v.w *= SCF;
    ((uint32_t*)Xh)[i * 2 + 0] = packh_hi2(v.x, v.y);
    ((uint32_t*)Xh)[i * 2 + 1] = packh_hi2(v.z, v.w);
    ((uint32_t*)Xl)[i * 2 + 0] = packh_lo2(v.x, v.y);
    ((uint32_t*)Xl)[i * 2 + 1] = packh_lo2(v.z, v.w);
}

// ---------------------------------------------------------------------------
// Transpose + scale: B fp32 [K,N] -> BhT fp16 scaled [N,K]
// ---------------------------------------------------------------------------
__global__ void split_bt_kernel(const float* __restrict__ B,
                                __half* __restrict__ BhT, int K, int N)
{
    __shared__ float t[32][33];
    const int tx = threadIdx.x, ty = threadIdx.y;
    const int n0 = blockIdx.x * 32, k0 = blockIdx.y * 32;
#pragma unroll
    for (int i = 0; i < 4; i++) {
        int k = ty + i * 8;
        t[k][tx] = B[(size_t)(k0 + k) * N + n0 + tx] * SCF;
    }
    __syncthreads();
#pragma unroll
    for (int i = 0; i < 4; i++) {
        int n = ty + i * 8;
        BhT[(size_t)(n0 + n) * K + k0 + tx] = __float2half_rn(t[tx][n]);
    }
}

// ---------------------------------------------------------------------------
// RoPE for Q -> scaled fp16 hi/lo
// ---------------------------------------------------------------------------
__global__ void rope_q_kernel(const float* __restrict__ qkv,
                              const int* __restrict__ positions,
                              __half* __restrict__ Qh,
                              __half* __restrict__ Ql)
{
    int idx = blockIdx.x * blockDim.x + threadIdx.x;
    int i  = idx & 63;
    int h  = (idx >> 6) & 31;
    int bs = idx >> 11;
    if (bs >= BSc) return;

    const float* src = qkv + (size_t)bs * QKVF + h * Dc;
    float x1 = src[i], x2 = src[i + 64];
    float pos = (float)positions[bs];
    float inv = 1.0f / powf(10000.0f, (float)i * (1.0f / 64.0f));
    float ang = pos * inv;
    float sn, cs;
    sincosf(ang, &sn, &cs);
    float y1 = (x1 * cs - x2 * sn) * SCF;
    float y2 = (x2 * cs + x1 * sn) * SCF;

    size_t o = (size_t)bs * (Hc * Dc) + h * Dc;
    __half h1 = __float2half_rn(y1);
    __half h2 = __float2half_rn(y2);
    Qh[o + i]      = h1;
    Qh[o + i + 64] = h2;
    Ql[o + i]      = __float2half_rn(y1 - __half2float(h1));
    Ql[o + i + 64] = __float2half_rn(y2 - __half2float(h2));
}

// ---------------------------------------------------------------------------
// Smooth conv + RoPE for K -> scaled fp16 hi
// ---------------------------------------------------------------------------
__global__ void smooth_rope_k_kernel(const float* __restrict__ qkv,
                                     const int* __restrict__ positions,
                                     const float* __restrict__ conv_k,
                                     __half* __restrict__ Kh)
{
    int idx = blockIdx.x * blockDim.x + threadIdx.x;
    int i  = idx & 63;
    int kv = (idx >> 6) & 7;
    int bs = idx >> 9;
    if (bs >= BSc) return;
    int s = bs & (Sc - 1);

    const float* src = qkv + (size_t)bs * QKVF + Hc * Dc + kv * Dc;
    float c1 = src[i], c2 = src[i + 64];
    float p1 = 0.f, p2 = 0.f;
    if (s > 0) {
        const float* ps = src - QKVF;
        p1 = ps[i]; p2 = ps[i + 64];
    }
    float f0 = conv_k[kv], f1 = conv_k[KVc + kv];
    float x1 = c1 * f1 + p1 * f0;
    float x2 = c2 * f1 + p2 * f0;

    float pos = (float)positions[bs];
    float inv = 1.0f / powf(10000.0f, (float)i * (1.0f / 64.0f));
    float ang = pos * inv;
    float sn, cs;
    sincosf(ang, &sn, &cs);

    size_t o = ((size_t)bs * KVc + kv) * Dc;
    Kh[o + i]      = __float2half_rn((x1 * cs - x2 * sn) * SCF);
    Kh[o + i + 64] = __float2half_rn((x2 * cs + x1 * sn) * SCF);
}

// ---------------------------------------------------------------------------
// Smooth conv for V + transpose -> scaled fp16 Vt hi [b][kv][d][s]
// ---------------------------------------------------------------------------
__global__ void smooth_v_t_kernel(const float* __restrict__ qkv,
                                  const float* __restrict__ conv_v,
                                  __half* __restrict__ Vth)
{
    __shared__ float t[32][33];
    const int tx = threadIdx.x, ty = threadIdx.y;
    const int s0 = blockIdx.x * 32;
    const int d0 = blockIdx.y * 32;
    const int b  = blockIdx.z >> 3;
    const int kv = blockIdx.z & 7;

    const float f0 = conv_v[kv], f1 = conv_v[KVc + kv];
    const size_t voff = (size_t)(Hc + KVc) * Dc + kv * Dc + d0;

#pragma unroll
    for (int i = 0; i < 4; i++) {
        int sl = ty + i * 8;
        int s = s0 + sl;
        const float* src = qkv + (size_t)(b * Sc + s) * QKVF + voff;
        float cur = src[tx];
        float prv = (s > 0) ? src[tx - QKVF] : 0.f;
        t[sl][tx] = (cur * f1 + prv * f0) * SCF;
    }
    __syncthreads();
#pragma unroll
    for (int i = 0; i < 4; i++) {
        int dl = ty + i * 8;
        size_t o = (((size_t)(b * KVc + kv)) * Dc + d0 + dl) * Sc + s0 + tx;
        Vth[o] = __float2half_rn(t[tx][dl]);
    }
}

// ---------------------------------------------------------------------------
// Register-resident windowed flash attention, fp16 2-term, 3-stage KV pipe.
// ---------------------------------------------------------------------------
#define RQK  272
#define RPV  144

#define A_QH   0
#define A_QL   (A_QH + 128 * RQK)
#define A_ST0  (A_QL + 128 * RQK)                   // 69632
#define KV_STAGE (64 * RQK + 128 * RPV)             // 35840
#define ST_KH  0
#define ST_VH  (64 * RQK)
#define ATTN_SMEM (A_ST0 + 3 * KV_STAGE)            // 177152

__global__ __launch_bounds__(256)
void attn_mma(const __half* __restrict__ Qh, const __half* __restrict__ Ql,
              const __half* __restrict__ Kh, const __half* __restrict__ Vth,
              __half* __restrict__ Oh, __half* __restrict__ Ol)
{
    extern __shared__ char sm[];
    const uint32_t sb = smem_u32(sm);

    const int tid  = threadIdx.x;
    const int w    = tid >> 5;
    const int lane = tid & 31;
    const int g  = lane >> 2;
    const int tg = lane & 3;

    const int qt = blockIdx.x, h = blockIdx.y, b = blockIdx.z;
    const int q0 = qt * 128;
    const int kvh = h >> 2;
    const float scale_eff = 0.08838834764831845f * INV_SC2;

    const uint32_t bmrow = (lane & 7) + (uint32_t)(lane >> 4) * 8;
    const uint32_t bcol  = ((lane >> 3) & 1) * 16;

    // ---- load Q tile (hi/lo) via cp.async (folds into first commit group) --
    {
        const size_t qbase = ((size_t)(b * Sc + q0) * Hc + h) * Dc;
#pragma unroll
        for (int hh = 0; hh < 8; hh++) {
            int idx = tid + hh * 256;
            int r = idx >> 4, u = idx & 15;
            const size_t go = qbase + (size_t)r * (Hc * Dc) + u * 8;
            cp16(sb + A_QH + r * RQK + u * 16, Qh + go);
            cp16(sb + A_QL + r * RQK + u * 16, Ql + go);
        }
    }

    const size_t kbase = ((size_t)b * Sc * KVc + kvh) * Dc;
    const size_t vbase = ((size_t)(b * KVc + kvh)) * Dc * Sc;
    auto load_kv = [&](int kt, int st) {
        const int k0 = kt * 64;
        const uint32_t stb = sb + A_ST0 + st * KV_STAGE;
#pragma unroll
        for (int hh = 0; hh < 4; hh++) {
            int idx = tid + hh * 256;
            int r = idx >> 4, u = idx & 15;
            const size_t go = kbase + (size_t)(k0 + r) * (KVc * Dc) + u * 8;
            cp16(stb + ST_KH + r * RQK + u * 16, Kh + go);
        }
#pragma unroll
        for (int hh = 0; hh < 4; hh++) {
            int idx = tid + hh * 256;
            int d = idx >> 3, u = idx & 7;
            const size_t go = vbase + (size_t)d * Sc + k0 + u * 8;
            cp16(stb + ST_VH + d * RPV + u * 16, Vth + go);
        }
    };

    float m0 = -1e30f, m1 = -1e30f, l0 = 0.f, l1 = 0.f;
    float oacc[16][4];
#pragma unroll
    for (int nt = 0; nt < 16; nt++)
#pragma unroll
        for (int j = 0; j < 4; j++) oacc[nt][j] = 0.f;

    const int qw_lo = q0 + w * 16;
    const int qw_hi = qw_lo + 15;
    const int qi0 = qw_lo + g;
    const int qi1 = qi0 + 8;

    int kt_lo = 2 * qt - 8; if (kt_lo < 0) kt_lo = 0;
    const int kt_hi = 2 * qt + 1;

    load_kv(kt_lo, 0);
    CP_COMMIT();
    if (kt_lo + 1 <= kt_hi) { load_kv(kt_lo + 1, 1); CP_COMMIT(); }

    uint32_t qfh[8][4], qfl[8][4];
    int stc = 0;

    for (int kt = kt_lo; kt <= kt_hi; kt++) {
        const int k0 = kt * 64;
        if (kt + 1 <= kt_hi) { CP_WAIT1(); } else { CP_WAIT0(); }
        __syncthreads();

        if (kt == kt_lo) {
            const uint32_t amrow = (lane & 7) + ((lane >> 3) & 1) * 8;
            const uint32_t acol  = (uint32_t)(lane >> 4) * 16;
#pragma unroll
            for (int ks = 0; ks < 8; ks++) {
                const uint32_t ar = (uint32_t)((w * 16 + amrow) * RQK) +
                                    (uint32_t)(ks * 32) + acol;
                ldsm_x4(qfh[ks], sb + A_QH + ar);
                ldsm_x4(qfl[ks], sb + A_QL + ar);
            }
        }

        if (kt + 2 <= kt_hi) {
            int stn = stc + 2; if (stn >= 3) stn -= 3;
            load_kv(kt + 2, stn);
            CP_COMMIT();
        }

        const uint32_t stb = sb + A_ST0 + stc * KV_STAGE;
        if (++stc == 3) stc = 0;

        if (k0 > qw_hi) continue;
        if (k0 + 575 <= qw_lo) continue;

        const uint32_t khb = stb + ST_KH;
        const uint32_t vhb = stb + ST_VH;

        // ---- scores: 2-term fp16 ----
        float sacc[8][4];
#pragma unroll
        for (int nt = 0; nt < 8; nt++)
#pragma unroll
            for (int j = 0; j < 4; j++) sacc[nt][j] = 0.f;

#pragma unroll
        for (int ks = 0; ks < 8; ks++) {
#pragma unroll
            for (int ntp = 0; ntp < 4; ntp++) {
                const uint32_t br = khb + (uint32_t)((ntp * 16 + bmrow) * RQK) +
                                    (uint32_t)(ks * 32) + bcol;
                uint32_t kh4[4];
                ldsm_x4(kh4, br);
                mma16816(sacc[2 * ntp],     qfh[ks], &kh4[0]);
                mma16816(sacc[2 * ntp],     qfl[ks], &kh4[0]);
                mma16816(sacc[2 * ntp + 1], qfh[ks], &kh4[2]);
                mma16816(sacc[2 * ntp + 1], qfl[ks], &kh4[2]);
            }
        }

        // ---- scale + mask ----
        const bool fully_valid = (k0 + 63 <= qw_lo) && (k0 >= qw_hi - (Wc - 1));
        if (fully_valid) {
#pragma unroll
            for (int nt = 0; nt < 8; nt++)
#pragma unroll
                for (int j = 0; j < 4; j++) sacc[nt][j] *= scale_eff;
        } else {
#pragma unroll
            for (int nt = 0; nt < 8; nt++) {
                const int ki0 = k0 + nt * 8 + tg * 2, ki1 = ki0 + 1;
                bool m00 = (ki0 <= qi0) && (qi0 - ki0 < Wc);
                bool m01 = (ki1 <= qi0) && (qi0 - ki1 < Wc);
                bool m10 = (ki0 <= qi1) && (qi1 - ki0 < Wc);
                bool m11 = (ki1 <= qi1) && (qi1 - ki1 < Wc);
                sacc[nt][0] = m00 ? sacc[nt][0] * scale_eff : -1e30f;
                sacc[nt][1] = m01 ? sacc[nt][1] * scale_eff : -1e30f;
                sacc[nt][2] = m10 ? sacc[nt][2] * scale_eff : -1e30f;
                sacc[nt][3] = m11 ? sacc[nt][3] * scale_eff : -1e30f;
            }
        }

        // ---- row max via shfl ----
        float mx0 = -1e30f, mx1 = -1e30f;
#pragma unroll
        for (int nt = 0; nt < 8; nt++) {
            mx0 = fmaxf(mx0, fmaxf(sacc[nt][0], sacc[nt][1]));
            mx1 = fmaxf(mx1, fmaxf(sacc[nt][2], sacc[nt][3]));
        }
        mx0 = fmaxf(mx0, __shfl_xor_sync(0xffffffffu, mx0, 1));
        mx0 = fmaxf(mx0, __shfl_xor_sync(0xffffffffu, mx0, 2));
        mx1 = fmaxf(mx1, __shfl_xor_sync(0xffffffffu, mx1, 1));
        mx1 = fmaxf(mx1, __shfl_xor_sync(0xffffffffu, mx1, 2));

        const float mn0 = fmaxf(m0, mx0);
        const float mn1 = fmaxf(m1, mx1);
        const float f0 = __expf(m0 - mn0);
        const float f1 = __expf(m1 - mn1);
        m0 = mn0; m1 = mn1;

        // ---- exp + sums ----
        float s0 = 0.f, s1 = 0.f;
#pragma unroll
        for (int nt = 0; nt < 8; nt++) {
            float p0 = (sacc[nt][0] > -1e29f) ? __expf(sacc[nt][0] - mn0) : 0.f;
            float p1 = (sacc[nt][1] > -1e29f) ? __expf(sacc[nt][1] - mn0) : 0.f;
            float p2 = (sacc[nt][2] > -1e29f) ? __expf(sacc[nt][2] - mn1) : 0.f;
            float p3 = (sacc[nt][3] > -1e29f) ? __expf(sacc[nt][3] - mn1) : 0.f;
            sacc[nt][0] = p0; sacc[nt][1] = p1; sacc[nt][2] = p2; sacc[nt][3] = p3;
            s0 += p0 + p1; s1 += p2 + p3;
        }
        s0 += __shfl_xor_sync(0xffffffffu, s0, 1);
        s0 += __shfl_xor_sync(0xffffffffu, s0, 2);
        s1 += __shfl_xor_sync(0xffffffffu, s1, 1);
        s1 += __shfl_xor_sync(0xffffffffu, s1, 2);
        l0 = l0 * f0 + s0;
        l1 = l1 * f1 + s1;

#pragma unroll
        for (int nt = 0; nt < 16; nt++) {
            oacc[nt][0] *= f0; oacc[nt][1] *= f0;
            oacc[nt][2] *= f1; oacc[nt][3] *= f1;
        }

        // ---- PV: P split to scaled fp16 hi/lo in registers ----
#pragma unroll
        for (int ks = 0; ks < 4; ks++) {
            uint32_t aph[4], apl[4];
            float c00 = sacc[2 * ks][0] * SCF,     c01 = sacc[2 * ks][1] * SCF;
            float c02 = sacc[2 * ks][2] * SCF,     c03 = sacc[2 * ks][3] * SCF;
            float c10 = sacc[2 * ks + 1][0] * SCF, c11 = sacc[2 * ks + 1][1] * SCF;
            float c12 = sacc[2 * ks + 1][2] * SCF, c13 = sacc[2 * ks + 1][3] * SCF;
            aph[0] = packh_hi2(c00, c01);
            aph[1] = packh_hi2(c02, c03);
            aph[2] = packh_hi2(c10, c11);
            aph[3] = packh_hi2(c12, c13);
            apl[0] = packh_lo2(c00, c01);
            apl[1] = packh_lo2(c02, c03);
            apl[2] = packh_lo2(c10, c11);
            apl[3] = packh_lo2(c12, c13);
#pragma unroll
            for (int ntp = 0; ntp < 8; ntp++) {
                const uint32_t br = vhb + (uint32_t)((ntp * 16 + bmrow) * RPV) +
                                    (uint32_t)(ks * 32) + bcol;
                uint32_t vh4[4];
                ldsm_x4(vh4, br);
                mma16816(oacc[2 * ntp],     aph, &vh4[0]);
                mma16816(oacc[2 * ntp],     apl, &vh4[0]);
                mma16816(oacc[2 * ntp + 1], aph, &vh4[2]);
                mma16816(oacc[2 * ntp + 1], apl, &vh4[2]);
            }
        }
    }

    // ---- epilogue ----
    {
        const float linv0 = (1.0f / l0) * (1.0f / SCF);
        const float linv1 = (1.0f / l1) * (1.0f / SCF);
        const size_t tok0 = (size_t)(b * Sc + qw_lo + g);
        const size_t tok1 = tok0 + 8;
#pragma unroll
        for (int nt = 0; nt < 16; nt++) {
            const int col = h * Dc + nt * 8 + tg * 2;
            float v00 = oacc[nt][0] * linv0, v01 = oacc[nt][1] * linv0;
            float v10 = oacc[nt][2] * linv1, v11 = oacc[nt][3] * linv1;
            ((uint32_t*)Oh)[(tok0 * HIDc + col) >> 1] = packh_hi2(v00, v01);
            ((uint32_t*)Ol)[(tok0 * HIDc + col) >> 1] = packh_lo2(v00, v01);
            ((uint32_t*)Oh)[(tok1 * HIDc + col) >> 1] = packh_hi2(v10, v11);
            ((uint32_t*)Ol)[(tok1 * HIDc + col) >> 1] = packh_lo2(v10, v11);
        }
    }
}

// ---------------------------------------------------------------------------
// Launch
// ---------------------------------------------------------------------------
extern "C" void kernel_launch(void* const* d_in, const int* in_sizes, int n_in,
                              void* d_out, int out_size)
{
    const float* hidden    = (const float*)d_in[0];
    const int*   positions = (const int*)d_in[1];
    const float* w_pack    = (const float*)d_in[2];
    const float* w_o       = (const float*)d_in[3];
    const float* conv_k    = (const float*)d_in[4];
    const float* conv_v    = (const float*)d_in[5];
    float* out = (float*)d_out;

    float* qkv;
    __half *qh, *ql, *kh, *vth, *ah, *al, *bh;
    cudaGetSymbolAddress((void**)&qkv, g_qkv);
    cudaGetSymbolAddress((void**)&qh,  g_qh);
    cudaGetSymbolAddress((void**)&ql,  g_ql);
    cudaGetSymbolAddress((void**)&kh,  g_kh);
    cudaGetSymbolAddress((void**)&vth, g_vth);
    cudaGetSymbolAddress((void**)&ah,  g_ah);
    cudaGetSymbolAddress((void**)&al,  g_al);
    cudaGetSymbolAddress((void**)&bh,  g_bh);

    cudaFuncSetAttribute(gemm_mma, cudaFuncAttributeMaxDynamicSharedMemorySize,
                         GEMM_SMEM);
    cudaFuncSetAttribute(attn_mma, cudaFuncAttributeMaxDynamicSharedMemorySize,
                         ATTN_SMEM);

    // ---- GEMM 1: qkv = hidden @ w_pack ----
    {
        int n4 = BSc * HIDc / 4;
        split_a_kernel<<<(n4 + 255) / 256, 256>>>(hidden, ah, al, n4);
        split_bt_kernel<<<dim3(QKVF / 32, HIDc / 32), dim3(32, 8)>>>(w_pack, bh, HIDc, QKVF);
        dim3 g1(QKVF / 128, BSc / 128);
        gemm_mma<<<g1, 256, GEMM_SMEM>>>(ah, al, bh, qkv, BSc, QKVF, HIDc);
    }

    // ---- elementwise prep (emit scaled fp16 operands) ----
    rope_q_kernel<<<(BSc * Hc * 64) / 256, 256>>>(qkv, positions, qh, ql);
    smooth_rope_k_kernel<<<(BSc * KVc * 64) / 256, 256>>>(qkv, positions, conv_k, kh);
    smooth_v_t_kernel<<<dim3(Sc / 32, Dc / 32, Bc * KVc), dim3(32, 8)>>>(qkv, conv_v, vth);

    // prep GEMM2 weights (hi only)
    split_bt_kernel<<<dim3(HIDc / 32, HIDc / 32), dim3(32, 8)>>>(w_o, bh, HIDc, HIDc);

    // ---- windowed attention; writes scaled fp16 A for GEMM2 ----
    attn_mma<<<dim3(Sc / 128, Hc, Bc), 256, ATTN_SMEM>>>(qh, ql, kh, vth, ah, al);

    // ---- GEMM 2: out = attn @ w_o ----
    {
        dim3 g2(HIDc / 128, BSc / 128);
        gemm_mma<<<g2, 256, GEMM_SMEM>>>(ah, al, bh, out, BSc, HIDc, HIDc);
    }
}

// round 10
// speedup vs baseline: 1.6385x; 1.6385x over previous
#include <cuda_runtime.h>
#include <cuda_fp16.h>
#include <math.h>
#include <stdint.h>

// ---------------------------------------------------------------------------
// Problem constants
// ---------------------------------------------------------------------------
#define Bc    2
#define Sc    2048
#define HIDc  4096
#define Hc    32
#define KVc   8
#define Dc    128
#define Wc    512
#define BSc   (Bc * Sc)              // 4096
#define QKVF  ((Hc + 2 * KVc) * Dc)  // 6144

// global operand scale 2^10
#define SCF      1024.0f
#define INV_SC2  (1.0f / (SCF * SCF))

// ---------------------------------------------------------------------------
// Scratch (static device globals -- no allocation allowed)
// ---------------------------------------------------------------------------
__device__ float g_qkv[(size_t)BSc * QKVF];

__device__ __half g_qh[(size_t)BSc * Hc * Dc];
__device__ __half g_kh[(size_t)BSc * KVc * Dc];
__device__ __half g_vth[(size_t)Bc * KVc * Dc * Sc];    // V^T [b][kv][d][s]

__device__ __half g_ah[(size_t)BSc * HIDc];             // GEMM A [M,K]
__device__ __half g_bh[(size_t)QKVF * HIDc];            // GEMM B^T [N,K]

// ---------------------------------------------------------------------------
// Helpers
// ---------------------------------------------------------------------------
__device__ __forceinline__ uint32_t smem_u32(const void* p) {
    uint32_t a;
    asm("{ .reg .u64 t; cvta.to.shared.u64 t, %1; cvt.u32.u64 %0, t; }"
        : "=r"(a) : "l"(p));
    return a;
}
__device__ __forceinline__ void cp16(uint32_t smem, const void* gmem) {
    asm volatile("cp.async.cg.shared.global [%0], [%1], 16;"
                 :: "r"(smem), "l"(gmem));
}
#define CP_COMMIT() asm volatile("cp.async.commit_group;" ::: "memory")
#define CP_WAIT0()  asm volatile("cp.async.wait_group 0;" ::: "memory")

__device__ __forceinline__ void ldsm_x4(uint32_t* r, uint32_t addr) {
    asm volatile("ldmatrix.sync.aligned.m8n8.x4.shared.b16 {%0,%1,%2,%3}, [%4];"
                 : "=r"(r[0]), "=r"(r[1]), "=r"(r[2]), "=r"(r[3]) : "r"(addr));
}

// fp16 HMMA m16n8k16, fp32 accumulate
__device__ __forceinline__ void mma16816(float* d, const uint32_t* a,
                                         const uint32_t* b) {
    asm volatile(
        "mma.sync.aligned.m16n8k16.row.col.f32.f16.f16.f32 "
        "{%0,%1,%2,%3}, {%4,%5,%6,%7}, {%8,%9}, {%0,%1,%2,%3};"
        : "+f"(d[0]), "+f"(d[1]), "+f"(d[2]), "+f"(d[3])
        : "r"(a[0]), "r"(a[1]), "r"(a[2]), "r"(a[3]),
          "r"(b[0]), "r"(b[1]));
}

__device__ __forceinline__ uint32_t packh2(float x, float y) {
    __half2 h(__float2half_rn(x), __float2half_rn(y));
    return *(uint32_t*)&h;
}

// ---------------------------------------------------------------------------
// fp16 HMMA GEMM:  C[M,N] = A[M,K] * B[K,N] / SC^2
// 2 CTAs/SM, ldmatrix, 2-stage cp.async double buffer.
// ---------------------------------------------------------------------------
#define GBK   32
#define SROW  40
#define MATB  (128 * SROW * 2)              // 10240 B
#define STAGEB (2 * MATB)                   // 20480 B (A, B)
#define GEMM_SMEM (2 * STAGEB)              // 40960 B

__global__ __launch_bounds__(256, 2)
void gemm_mma(const __half* __restrict__ Ah,
              const __half* __restrict__ Bh,
              float* __restrict__ C, int M, int N, int K)
{
    extern __shared__ char sm[];
    const uint32_t sb = smem_u32(sm);
    const int tid  = threadIdx.x;
    const int wid  = tid >> 5;
    const int lane = tid & 31;
    const int wm = wid & 3;
    const int wn = wid >> 2;
    const int g  = lane >> 2;
    const int tg = lane & 3;

    const int m0 = blockIdx.y * 128;
    const int n0 = blockIdx.x * 128;

    const uint32_t amrow = (lane & 7) + ((lane >> 3) & 1) * 8;
    const uint32_t acol  = (uint32_t)(lane >> 4) * 16;
    const uint32_t bmrow = (lane & 7) + (uint32_t)(lane >> 4) * 8;
    const uint32_t bcol  = ((lane >> 3) & 1) * 16;

    auto load_stage = [&](int k0, int st) {
        const uint32_t base = sb + st * STAGEB;
#pragma unroll
        for (int mat = 0; mat < 2; mat++) {
            const __half* src = (mat == 0) ? Ah : Bh;
            const int row0 = (mat == 0) ? m0 : n0;
#pragma unroll
            for (int hh = 0; hh < 2; hh++) {
                int unit = tid + hh * 256;
                int r = unit >> 2, u = unit & 3;
                const void* gp = src + (size_t)(row0 + r) * K + k0 + u * 8;
                cp16(base + mat * MATB + r * (SROW * 2) + u * 16, gp);
            }
        }
    };

    float acc[2][8][4];
#pragma unroll
    for (int mt = 0; mt < 2; mt++)
#pragma unroll
        for (int nt = 0; nt < 8; nt++)
#pragma unroll
            for (int j = 0; j < 4; j++) acc[mt][nt][j] = 0.f;

    const int NIT = K / GBK;
    load_stage(0, 0);
    CP_COMMIT();

    for (int it = 0; it < NIT; it++) {
        CP_WAIT0();
        __syncthreads();
        const int st = it & 1;
        if (it + 1 < NIT) {
            load_stage((it + 1) * GBK, st ^ 1);
            CP_COMMIT();
        }

        const uint32_t ahb = sb + st * STAGEB;
        const uint32_t bhb = ahb + MATB;

#pragma unroll
        for (int ks = 0; ks < 2; ks++) {
            uint32_t ah[2][4];
#pragma unroll
            for (int mt = 0; mt < 2; mt++) {
                const uint32_t ar = ahb +
                    (uint32_t)((wm * 32 + mt * 16 + amrow) * (SROW * 2)) +
                    (uint32_t)(ks * 32) + acol;
                ldsm_x4(ah[mt], ar);
            }
#pragma unroll
            for (int ntp = 0; ntp < 4; ntp++) {
                const uint32_t br = bhb +
                    (uint32_t)((wn * 64 + ntp * 16 + bmrow) * (SROW * 2)) +
                    (uint32_t)(ks * 32) + bcol;
                uint32_t bh4[4];
                ldsm_x4(bh4, br);
#pragma unroll
                for (int mt = 0; mt < 2; mt++) {
                    mma16816(acc[mt][2 * ntp],     ah[mt], &bh4[0]);
                    mma16816(acc[mt][2 * ntp + 1], ah[mt], &bh4[2]);
                }
            }
        }
    }

#pragma unroll
    for (int mt = 0; mt < 2; mt++) {
        const int r0 = m0 + wm * 32 + mt * 16 + g;
#pragma unroll
        for (int nt = 0; nt < 8; nt++) {
            const int cc = n0 + wn * 64 + nt * 8 + tg * 2;
            float2 w0 = make_float2(acc[mt][nt][0] * INV_SC2,
                                    acc[mt][nt][1] * INV_SC2);
            float2 w1 = make_float2(acc[mt][nt][2] * INV_SC2,
                                    acc[mt][nt][3] * INV_SC2);
            *(float2*)(C + (size_t)r0 * N + cc)       = w0;
            *(float2*)(C + (size_t)(r0 + 8) * N + cc) = w1;
        }
    }
}

// ---------------------------------------------------------------------------
// Convert fp32 -> scaled fp16
// ---------------------------------------------------------------------------
__global__ void conv_a_kernel(const float* __restrict__ X,
                              __half* __restrict__ Xh, int n4)
{
    int i = blockIdx.x * blockDim.x + threadIdx.x;
    if (i >= n4) return;
    float4 v = ((const float4*)X)[i];
    ((uint32_t*)Xh)[i * 2 + 0] = packh2(v.x * SCF, v.y * SCF);
    ((uint32_t*)Xh)[i * 2 + 1] = packh2(v.z * SCF, v.w * SCF);
}

// ---------------------------------------------------------------------------
// Transpose + scale: B fp32 [K,N] -> BhT fp16 scaled [N,K]
// ---------------------------------------------------------------------------
__global__ void conv_bt_kernel(const float* __restrict__ B,
                               __half* __restrict__ BhT, int K, int N)
{
    __shared__ float t[32][33];
    const int tx = threadIdx.x, ty = threadIdx.y;
    const int n0 = blockIdx.x * 32, k0 = blockIdx.y * 32;
#pragma unroll
    for (int i = 0; i < 4; i++) {
        int k = ty + i * 8;
        t[k][tx] = B[(size_t)(k0 + k) * N + n0 + tx] * SCF;
    }
    __syncthreads();
#pragma unroll
    for (int i = 0; i < 4; i++) {
        int n = ty + i * 8;
        BhT[(size_t)(n0 + n) * K + k0 + tx] = __float2half_rn(t[tx][n]);
    }
}

// ---------------------------------------------------------------------------
// RoPE for Q -> scaled fp16
// ---------------------------------------------------------------------------
__global__ void rope_q_kernel(const float* __restrict__ qkv,
                              const int* __restrict__ positions,
                              __half* __restrict__ Qh)
{
    int idx = blockIdx.x * blockDim.x + threadIdx.x;
    int i  = idx & 63;
    int h  = (idx >> 6) & 31;
    int bs = idx >> 11;
    if (bs >= BSc) return;

    const float* src = qkv + (size_t)bs * QKVF + h * Dc;
    float x1 = src[i], x2 = src[i + 64];
    float pos = (float)positions[bs];
    float inv = 1.0f / powf(10000.0f, (float)i * (1.0f / 64.0f));
    float ang = pos * inv;
    float sn, cs;
    sincosf(ang, &sn, &cs);

    size_t o = (size_t)bs * (Hc * Dc) + h * Dc;
    Qh[o + i]      = __float2half_rn((x1 * cs - x2 * sn) * SCF);
    Qh[o + i + 64] = __float2half_rn((x2 * cs + x1 * sn) * SCF);
}

// ---------------------------------------------------------------------------
// Smooth conv + RoPE for K -> scaled fp16
// ---------------------------------------------------------------------------
__global__ void smooth_rope_k_kernel(const float* __restrict__ qkv,
                                     const int* __restrict__ positions,
                                     const float* __restrict__ conv_k,
                                     __half* __restrict__ Kh)
{
    int idx = blockIdx.x * blockDim.x + threadIdx.x;
    int i  = idx & 63;
    int kv = (idx >> 6) & 7;
    int bs = idx >> 9;
    if (bs >= BSc) return;
    int s = bs & (Sc - 1);

    const float* src = qkv + (size_t)bs * QKVF + Hc * Dc + kv * Dc;
    float c1 = src[i], c2 = src[i + 64];
    float p1 = 0.f, p2 = 0.f;
    if (s > 0) {
        const float* ps = src - QKVF;
        p1 = ps[i]; p2 = ps[i + 64];
    }
    float f0 = conv_k[kv], f1 = conv_k[KVc + kv];
    float x1 = c1 * f1 + p1 * f0;
    float x2 = c2 * f1 + p2 * f0;

    float pos = (float)positions[bs];
    float inv = 1.0f / powf(10000.0f, (float)i * (1.0f / 64.0f));
    float ang = pos * inv;
    float sn, cs;
    sincosf(ang, &sn, &cs);

    size_t o = ((size_t)bs * KVc + kv) * Dc;
    Kh[o + i]      = __float2half_rn((x1 * cs - x2 * sn) * SCF);
    Kh[o + i + 64] = __float2half_rn((x2 * cs + x1 * sn) * SCF);
}

// ---------------------------------------------------------------------------
// Smooth conv for V + transpose -> scaled fp16 Vt [b][kv][d][s]
// ---------------------------------------------------------------------------
__global__ void smooth_v_t_kernel(const float* __restrict__ qkv,
                                  const float* __restrict__ conv_v,
                                  __half* __restrict__ Vth)
{
    __shared__ float t[32][33];
    const int tx = threadIdx.x, ty = threadIdx.y;
    const int s0 = blockIdx.x * 32;
    const int d0 = blockIdx.y * 32;
    const int b  = blockIdx.z >> 3;
    const int kv = blockIdx.z & 7;

    const float f0 = conv_v[kv], f1 = conv_v[KVc + kv];
    const size_t voff = (size_t)(Hc + KVc) * Dc + kv * Dc + d0;

#pragma unroll
    for (int i = 0; i < 4; i++) {
        int sl = ty + i * 8;
        int s = s0 + sl;
        const float* src = qkv + (size_t)(b * Sc + s) * QKVF + voff;
        float cur = src[tx];
        float prv = (s > 0) ? src[tx - QKVF] : 0.f;
        t[sl][tx] = (cur * f1 + prv * f0) * SCF;
    }
    __syncthreads();
#pragma unroll
    for (int i = 0; i < 4; i++) {
        int dl = ty + i * 8;
        size_t o = (((size_t)(b * KVc + kv)) * Dc + d0 + dl) * Sc + s0 + tx;
        Vth[o] = __float2half_rn(t[tx][dl]);
    }
}

// ---------------------------------------------------------------------------
// Register-resident windowed flash attention, pure fp16 operands.
// ---------------------------------------------------------------------------
#define RQK  272
#define RPV  144

#define A_QH   0
#define A_ST0  (A_QH + 128 * RQK)                   // 34816
#define KV_STAGE (64 * RQK + 128 * RPV)             // 35840
#define ST_KH  0
#define ST_VH  (64 * RQK)
#define ATTN_SMEM (A_ST0 + 2 * KV_STAGE)            // 106496

__global__ __launch_bounds__(256)
void attn_mma(const __half* __restrict__ Qh,
              const __half* __restrict__ Kh, const __half* __restrict__ Vth,
              __half* __restrict__ Oh)
{
    extern __shared__ char sm[];
    const uint32_t sb = smem_u32(sm);

    const int tid  = threadIdx.x;
    const int w    = tid >> 5;
    const int lane = tid & 31;
    const int g  = lane >> 2;
    const int tg = lane & 3;

    const int qt = blockIdx.x, h = blockIdx.y, b = blockIdx.z;
    const int q0 = qt * 128;
    const int kvh = h >> 2;
    const float scale_eff = 0.08838834764831845f * INV_SC2;

    const uint32_t bmrow = (lane & 7) + (uint32_t)(lane >> 4) * 8;
    const uint32_t bcol  = ((lane >> 3) & 1) * 16;

    // ---- load Q tile via cp.async ----
    {
        const size_t qbase = ((size_t)(b * Sc + q0) * Hc + h) * Dc;
#pragma unroll
        for (int hh = 0; hh < 8; hh++) {
            int idx = tid + hh * 256;
            int r = idx >> 4, u = idx & 15;
            const size_t go = qbase + (size_t)r * (Hc * Dc) + u * 8;
            cp16(sb + A_QH + r * RQK + u * 16, Qh + go);
        }
    }

    const size_t kbase = ((size_t)b * Sc * KVc + kvh) * Dc;
    const size_t vbase = ((size_t)(b * KVc + kvh)) * Dc * Sc;
    auto load_kv = [&](int kt, int st) {
        const int k0 = kt * 64;
        const uint32_t stb = sb + A_ST0 + st * KV_STAGE;
#pragma unroll
        for (int hh = 0; hh < 4; hh++) {
            int idx = tid + hh * 256;
            int r = idx >> 4, u = idx & 15;
            const size_t go = kbase + (size_t)(k0 + r) * (KVc * Dc) + u * 8;
            cp16(stb + ST_KH + r * RQK + u * 16, Kh + go);
        }
#pragma unroll
        for (int hh = 0; hh < 4; hh++) {
            int idx = tid + hh * 256;
            int d = idx >> 3, u = idx & 7;
            const size_t go = vbase + (size_t)d * Sc + k0 + u * 8;
            cp16(stb + ST_VH + d * RPV + u * 16, Vth + go);
        }
    };

    float m0 = -1e30f, m1 = -1e30f, l0 = 0.f, l1 = 0.f;
    float oacc[16][4];
#pragma unroll
    for (int nt = 0; nt < 16; nt++)
#pragma unroll
        for (int j = 0; j < 4; j++) oacc[nt][j] = 0.f;

    const int qw_lo = q0 + w * 16;
    const int qw_hi = qw_lo + 15;
    const int qi0 = qw_lo + g;
    const int qi1 = qi0 + 8;

    int kt_lo = 2 * qt - 8; if (kt_lo < 0) kt_lo = 0;
    const int kt_hi = 2 * qt + 1;

    load_kv(kt_lo, 0);
    CP_COMMIT();

    uint32_t qfh[8][4];

    for (int kt = kt_lo; kt <= kt_hi; kt++) {
        const int st = (kt - kt_lo) & 1;
        const int k0 = kt * 64;
        CP_WAIT0();
        __syncthreads();

        if (kt == kt_lo) {
            const uint32_t amrow = (lane & 7) + ((lane >> 3) & 1) * 8;
            const uint32_t acol  = (uint32_t)(lane >> 4) * 16;
#pragma unroll
            for (int ks = 0; ks < 8; ks++) {
                const uint32_t ar = (uint32_t)((w * 16 + amrow) * RQK) +
                                    (uint32_t)(ks * 32) + acol;
                ldsm_x4(qfh[ks], sb + A_QH + ar);
            }
        }

        if (kt < kt_hi) {
            load_kv(kt + 1, st ^ 1);
            CP_COMMIT();
        }

        if (k0 > qw_hi) continue;
        if (k0 + 575 <= qw_lo) continue;

        const uint32_t stb = sb + A_ST0 + st * KV_STAGE;
        const uint32_t khb = stb + ST_KH;
        const uint32_t vhb = stb + ST_VH;

        // ---- scores (1-term fp16) ----
        float sacc[8][4];
#pragma unroll
        for (int nt = 0; nt < 8; nt++)
#pragma unroll
            for (int j = 0; j < 4; j++) sacc[nt][j] = 0.f;

#pragma unroll
        for (int ks = 0; ks < 8; ks++) {
#pragma unroll
            for (int ntp = 0; ntp < 4; ntp++) {
                const uint32_t br = khb + (uint32_t)((ntp * 16 + bmrow) * RQK) +
                                    (uint32_t)(ks * 32) + bcol;
                uint32_t kh4[4];
                ldsm_x4(kh4, br);
                mma16816(sacc[2 * ntp],     qfh[ks], &kh4[0]);
                mma16816(sacc[2 * ntp + 1], qfh[ks], &kh4[2]);
            }
        }

        // ---- scale + mask ----
        const bool fully_valid = (k0 + 63 <= qw_lo) && (k0 >= qw_hi - (Wc - 1));
        if (fully_valid) {
#pragma unroll
            for (int nt = 0; nt < 8; nt++)
#pragma unroll
                for (int j = 0; j < 4; j++) sacc[nt][j] *= scale_eff;
        } else {
#pragma unroll
            for (int nt = 0; nt < 8; nt++) {
                const int ki0 = k0 + nt * 8 + tg * 2, ki1 = ki0 + 1;
                bool m00 = (ki0 <= qi0) && (qi0 - ki0 < Wc);
                bool m01 = (ki1 <= qi0) && (qi0 - ki1 < Wc);
                bool m10 = (ki0 <= qi1) && (qi1 - ki0 < Wc);
                bool m11 = (ki1 <= qi1) && (qi1 - ki1 < Wc);
                sacc[nt][0] = m00 ? sacc[nt][0] * scale_eff : -1e30f;
                sacc[nt][1] = m01 ? sacc[nt][1] * scale_eff : -1e30f;
                sacc[nt][2] = m10 ? sacc[nt][2] * scale_eff : -1e30f;
                sacc[nt][3] = m11 ? sacc[nt][3] * scale_eff : -1e30f;
            }
        }

        // ---- row max via shfl ----
        float mx0 = -1e30f, mx1 = -1e30f;
#pragma unroll
        for (int nt = 0; nt < 8; nt++) {
            mx0 = fmaxf(mx0, fmaxf(sacc[nt][0], sacc[nt][1]));
            mx1 = fmaxf(mx1, fmaxf(sacc[nt][2], sacc[nt][3]));
        }
        mx0 = fmaxf(mx0, __shfl_xor_sync(0xffffffffu, mx0, 1));
        mx0 = fmaxf(mx0, __shfl_xor_sync(0xffffffffu, mx0, 2));
        mx1 = fmaxf(mx1, __shfl_xor_sync(0xffffffffu, mx1, 1));
        mx1 = fmaxf(mx1, __shfl_xor_sync(0xffffffffu, mx1, 2));

        const float mn0 = fmaxf(m0, mx0);
        const float mn1 = fmaxf(m1, mx1);
        const float f0 = __expf(m0 - mn0);
        const float f1 = __expf(m1 - mn1);
        m0 = mn0; m1 = mn1;

        // ---- exp + sums ----
        float s0 = 0.f, s1 = 0.f;
#pragma unroll
        for (int nt = 0; nt < 8; nt++) {
            float p0 = (sacc[nt][0] > -1e29f) ? __expf(sacc[nt][0] - mn0) : 0.f;
            float p1 = (sacc[nt][1] > -1e29f) ? __expf(sacc[nt][1] - mn0) : 0.f;
            float p2 = (sacc[nt][2] > -1e29f) ? __expf(sacc[nt][2] - mn1) : 0.f;
            float p3 = (sacc[nt][3] > -1e29f) ? __expf(sacc[nt][3] - mn1) : 0.f;
            sacc[nt][0] = p0; sacc[nt][1] = p1; sacc[nt][2] = p2; sacc[nt][3] = p3;
            s0 += p0 + p1; s1 += p2 + p3;
        }
        s0 += __shfl_xor_sync(0xffffffffu, s0, 1);
        s0 += __shfl_xor_sync(0xffffffffu, s0, 2);
        s1 += __shfl_xor_sync(0xffffffffu, s1, 1);
        s1 += __shfl_xor_sync(0xffffffffu, s1, 2);
        l0 = l0 * f0 + s0;
        l1 = l1 * f1 + s1;

#pragma unroll
        for (int nt = 0; nt < 16; nt++) {
            oacc[nt][0] *= f0; oacc[nt][1] *= f0;
            oacc[nt][2] *= f1; oacc[nt][3] *= f1;
        }

        // ---- PV (1-term fp16; P scaled to SCF) ----
#pragma unroll
        for (int ks = 0; ks < 4; ks++) {
            uint32_t aph[4];
            aph[0] = packh2(sacc[2 * ks][0] * SCF,     sacc[2 * ks][1] * SCF);
            aph[1] = packh2(sacc[2 * ks][2] * SCF,     sacc[2 * ks][3] * SCF);
            aph[2] = packh2(sacc[2 * ks + 1][0] * SCF, sacc[2 * ks + 1][1] * SCF);
            aph[3] = packh2(sacc[2 * ks + 1][2] * SCF, sacc[2 * ks + 1][3] * SCF);
#pragma unroll
            for (int ntp = 0; ntp < 8; ntp++) {
                const uint32_t br = vhb + (uint32_t)((ntp * 16 + bmrow) * RPV) +
                                    (uint32_t)(ks * 32) + bcol;
                uint32_t vh4[4];
                ldsm_x4(vh4, br);
                mma16816(oacc[2 * ntp],     aph, &vh4[0]);
                mma16816(oacc[2 * ntp + 1], aph, &vh4[2]);
            }
        }
    }

    // ---- epilogue: normalize, rescale to fp16 GEMM2 A operand ----
    {
        // oacc carries SC^2; operand needs value*SC -> /SC
        const float linv0 = (1.0f / l0) * (1.0f / SCF);
        const float linv1 = (1.0f / l1) * (1.0f / SCF);
        const size_t tok0 = (size_t)(b * Sc + qw_lo + g);
        const size_t tok1 = tok0 + 8;
#pragma unroll
        for (int nt = 0; nt < 16; nt++) {
            const int col = h * Dc + nt * 8 + tg * 2;
            ((uint32_t*)Oh)[(tok0 * HIDc + col) >> 1] =
                packh2(oacc[nt][0] * linv0, oacc[nt][1] * linv0);
            ((uint32_t*)Oh)[(tok1 * HIDc + col) >> 1] =
                packh2(oacc[nt][2] * linv1, oacc[nt][3] * linv1);
        }
    }
}

// ---------------------------------------------------------------------------
// Launch
// ---------------------------------------------------------------------------
extern "C" void kernel_launch(void* const* d_in, const int* in_sizes, int n_in,
                              void* d_out, int out_size)
{
    const float* hidden    = (const float*)d_in[0];
    const int*   positions = (const int*)d_in[1];
    const float* w_pack    = (const float*)d_in[2];
    const float* w_o       = (const float*)d_in[3];
    const float* conv_k    = (const float*)d_in[4];
    const float* conv_v    = (const float*)d_in[5];
    float* out = (float*)d_out;

    float* qkv;
    __half *qh, *kh, *vth, *ah, *bh;
    cudaGetSymbolAddress((void**)&qkv, g_qkv);
    cudaGetSymbolAddress((void**)&qh,  g_qh);
    cudaGetSymbolAddress((void**)&kh,  g_kh);
    cudaGetSymbolAddress((void**)&vth, g_vth);
    cudaGetSymbolAddress((void**)&ah,  g_ah);
    cudaGetSymbolAddress((void**)&bh,  g_bh);

    cudaFuncSetAttribute(gemm_mma, cudaFuncAttributeMaxDynamicSharedMemorySize,
                         GEMM_SMEM);
    cudaFuncSetAttribute(attn_mma, cudaFuncAttributeMaxDynamicSharedMemorySize,
                         ATTN_SMEM);

    // ---- GEMM 1: qkv = hidden @ w_pack ----
    {
        int n4 = BSc * HIDc / 4;
        conv_a_kernel<<<(n4 + 255) / 256, 256>>>(hidden, ah, n4);
        conv_bt_kernel<<<dim3(QKVF / 32, HIDc / 32), dim3(32, 8)>>>(w_pack, bh, HIDc, QKVF);
        dim3 g1(QKVF / 128, BSc / 128);
        gemm_mma<<<g1, 256, GEMM_SMEM>>>(ah, bh, qkv, BSc, QKVF, HIDc);
    }

    // ---- elementwise prep (emit scaled fp16 operands) ----
    rope_q_kernel<<<(BSc * Hc * 64) / 256, 256>>>(qkv, positions, qh);
    smooth_rope_k_kernel<<<(BSc * KVc * 64) / 256, 256>>>(qkv, positions, conv_k, kh);
    smooth_v_t_kernel<<<dim3(Sc / 32, Dc / 32, Bc * KVc), dim3(32, 8)>>>(qkv, conv_v, vth);

    // prep GEMM2 weights
    conv_bt_kernel<<<dim3(HIDc / 32, HIDc / 32), dim3(32, 8)>>>(w_o, bh, HIDc, HIDc);

    // ---- windowed attention; writes fp16 A for GEMM2 ----
    attn_mma<<<dim3(Sc / 128, Hc, Bc), 256, ATTN_SMEM>>>(qh, kh, vth, ah);

    // ---- GEMM 2: out = attn @ w_o ----
    {
        dim3 g2(HIDc / 128, BSc / 128);
        gemm_mma<<<g2, 256, GEMM_SMEM>>>(ah, bh, out, BSc, HIDc, HIDc);
    }
}

// round 11
// speedup vs baseline: 1.8328x; 1.1186x over previous
#include <cuda_runtime.h>
#include <cuda_fp16.h>
#include <math.h>
#include <stdint.h>

// ---------------------------------------------------------------------------
// Problem constants
// ---------------------------------------------------------------------------
#define Bc    2
#define Sc    2048
#define HIDc  4096
#define Hc    32
#define KVc   8
#define Dc    128
#define Wc    512
#define BSc   (Bc * Sc)              // 4096
#define QKVF  ((Hc + 2 * KVc) * Dc)  // 6144

// global operand scale 2^10
#define SCF      1024.0f
#define INV_SC2  (1.0f / (SCF * SCF))

// ---------------------------------------------------------------------------
// Scratch (static device globals -- no allocation allowed)
// ---------------------------------------------------------------------------
__device__ float g_qkv[(size_t)BSc * QKVF];

__device__ __half g_qh[(size_t)BSc * Hc * Dc];
__device__ __half g_kh[(size_t)BSc * KVc * Dc];
__device__ __half g_vth[(size_t)Bc * KVc * Dc * Sc];    // V^T [b][kv][d][s]

__device__ __half g_ah[(size_t)BSc * HIDc];             // GEMM A [M,K]
__device__ __half g_bh[(size_t)QKVF * HIDc];            // GEMM B^T [N,K]

// ---------------------------------------------------------------------------
// Helpers
// ---------------------------------------------------------------------------
__device__ __forceinline__ uint32_t smem_u32(const void* p) {
    uint32_t a;
    asm("{ .reg .u64 t; cvta.to.shared.u64 t, %1; cvt.u32.u64 %0, t; }"
        : "=r"(a) : "l"(p));
    return a;
}
__device__ __forceinline__ void cp16(uint32_t smem, const void* gmem) {
    asm volatile("cp.async.cg.shared.global [%0], [%1], 16;"
                 :: "r"(smem), "l"(gmem));
}
#define CP_COMMIT() asm volatile("cp.async.commit_group;" ::: "memory")
#define CP_WAIT0()  asm volatile("cp.async.wait_group 0;" ::: "memory")

__device__ __forceinline__ void ldsm_x4(uint32_t* r, uint32_t addr) {
    asm volatile("ldmatrix.sync.aligned.m8n8.x4.shared.b16 {%0,%1,%2,%3}, [%4];"
                 : "=r"(r[0]), "=r"(r[1]), "=r"(r[2]), "=r"(r[3]) : "r"(addr));
}

// fp16 HMMA m16n8k16, fp32 accumulate
__device__ __forceinline__ void mma16816(float* d, const uint32_t* a,
                                         const uint32_t* b) {
    asm volatile(
        "mma.sync.aligned.m16n8k16.row.col.f32.f16.f16.f32 "
        "{%0,%1,%2,%3}, {%4,%5,%6,%7}, {%8,%9}, {%0,%1,%2,%3};"
        : "+f"(d[0]), "+f"(d[1]), "+f"(d[2]), "+f"(d[3])
        : "r"(a[0]), "r"(a[1]), "r"(a[2]), "r"(a[3]),
          "r"(b[0]), "r"(b[1]));
}

__device__ __forceinline__ uint32_t packh2(float x, float y) {
    __half2 h(__float2half_rn(x), __float2half_rn(y));
    return *(uint32_t*)&h;
}

// ---------------------------------------------------------------------------
// fp16 HMMA GEMM:  C[M,N] = A[M,K] * B[K,N] / SC^2
// 2 CTAs/SM, ldmatrix, 2-stage cp.async double buffer, BK=64.
// ---------------------------------------------------------------------------
#define GBK   64
#define SROW  72                            // smem row stride in halves (144 B)
#define MATB  (128 * SROW * 2)              // 18432 B
#define STAGEB (2 * MATB)                   // 36864 B (A, B)
#define GEMM_SMEM (2 * STAGEB)              // 73728 B

__global__ __launch_bounds__(256, 2)
void gemm_mma(const __half* __restrict__ Ah,
              const __half* __restrict__ Bh,
              float* __restrict__ C, int M, int N, int K)
{
    extern __shared__ char sm[];
    const uint32_t sb = smem_u32(sm);
    const int tid  = threadIdx.x;
    const int wid  = tid >> 5;
    const int lane = tid & 31;
    const int wm = wid & 3;
    const int wn = wid >> 2;
    const int g  = lane >> 2;
    const int tg = lane & 3;

    const int m0 = blockIdx.y * 128;
    const int n0 = blockIdx.x * 128;

    const uint32_t amrow = (lane & 7) + ((lane >> 3) & 1) * 8;
    const uint32_t acol  = (uint32_t)(lane >> 4) * 16;
    const uint32_t bmrow = (lane & 7) + (uint32_t)(lane >> 4) * 8;
    const uint32_t bcol  = ((lane >> 3) & 1) * 16;

    // stage loader: A and B tiles, 128 rows x 128 B each = 1024 16B units/mat
    auto load_stage = [&](int k0, int st) {
        const uint32_t base = sb + st * STAGEB;
#pragma unroll
        for (int mat = 0; mat < 2; mat++) {
            const __half* src = (mat == 0) ? Ah : Bh;
            const int row0 = (mat == 0) ? m0 : n0;
#pragma unroll
            for (int hh = 0; hh < 4; hh++) {
                int unit = tid + hh * 256;
                int r = unit >> 3, u = unit & 7;
                const void* gp = src + (size_t)(row0 + r) * K + k0 + u * 8;
                cp16(base + mat * MATB + r * (SROW * 2) + u * 16, gp);
            }
        }
    };

    float acc[2][8][4];
#pragma unroll
    for (int mt = 0; mt < 2; mt++)
#pragma unroll
        for (int nt = 0; nt < 8; nt++)
#pragma unroll
            for (int j = 0; j < 4; j++) acc[mt][nt][j] = 0.f;

    const int NIT = K / GBK;                // 64 iterations for K=4096
    load_stage(0, 0);
    CP_COMMIT();

    for (int it = 0; it < NIT; it++) {
        CP_WAIT0();
        __syncthreads();
        const int st = it & 1;
        if (it + 1 < NIT) {
            load_stage((it + 1) * GBK, st ^ 1);
            CP_COMMIT();
        }

        const uint32_t ahb = sb + st * STAGEB;
        const uint32_t bhb = ahb + MATB;

#pragma unroll
        for (int ks = 0; ks < 4; ks++) {
            uint32_t ah[2][4];
#pragma unroll
            for (int mt = 0; mt < 2; mt++) {
                const uint32_t ar = ahb +
                    (uint32_t)((wm * 32 + mt * 16 + amrow) * (SROW * 2)) +
                    (uint32_t)(ks * 32) + acol;
                ldsm_x4(ah[mt], ar);
            }
#pragma unroll
            for (int ntp = 0; ntp < 4; ntp++) {
                const uint32_t br = bhb +
                    (uint32_t)((wn * 64 + ntp * 16 + bmrow) * (SROW * 2)) +
                    (uint32_t)(ks * 32) + bcol;
                uint32_t bh4[4];
                ldsm_x4(bh4, br);
#pragma unroll
                for (int mt = 0; mt < 2; mt++) {
                    mma16816(acc[mt][2 * ntp],     ah[mt], &bh4[0]);
                    mma16816(acc[mt][2 * ntp + 1], ah[mt], &bh4[2]);
                }
            }
        }
    }

#pragma unroll
    for (int mt = 0; mt < 2; mt++) {
        const int r0 = m0 + wm * 32 + mt * 16 + g;
#pragma unroll
        for (int nt = 0; nt < 8; nt++) {
            const int cc = n0 + wn * 64 + nt * 8 + tg * 2;
            float2 w0 = make_float2(acc[mt][nt][0] * INV_SC2,
                                    acc[mt][nt][1] * INV_SC2);
            float2 w1 = make_float2(acc[mt][nt][2] * INV_SC2,
                                    acc[mt][nt][3] * INV_SC2);
            *(float2*)(C + (size_t)r0 * N + cc)       = w0;
            *(float2*)(C + (size_t)(r0 + 8) * N + cc) = w1;
        }
    }
}

// ---------------------------------------------------------------------------
// Convert fp32 -> scaled fp16
// ---------------------------------------------------------------------------
__global__ void conv_a_kernel(const float* __restrict__ X,
                              __half* __restrict__ Xh, int n4)
{
    int i = blockIdx.x * blockDim.x + threadIdx.x;
    if (i >= n4) return;
    float4 v = ((const float4*)X)[i];
    ((uint32_t*)Xh)[i * 2 + 0] = packh2(v.x * SCF, v.y * SCF);
    ((uint32_t*)Xh)[i * 2 + 1] = packh2(v.z * SCF, v.w * SCF);
}

// ---------------------------------------------------------------------------
// Transpose + scale: B fp32 [K,N] -> BhT fp16 scaled [N,K]
// ---------------------------------------------------------------------------
__global__ void conv_bt_kernel(const float* __restrict__ B,
                               __half* __restrict__ BhT, int K, int N)
{
    __shared__ float t[32][33];
    const int tx = threadIdx.x, ty = threadIdx.y;
    const int n0 = blockIdx.x * 32, k0 = blockIdx.y * 32;
#pragma unroll
    for (int i = 0; i < 4; i++) {
        int k = ty + i * 8;
        t[k][tx] = B[(size_t)(k0 + k) * N + n0 + tx] * SCF;
    }
    __syncthreads();
#pragma unroll
    for (int i = 0; i < 4; i++) {
        int n = ty + i * 8;
        BhT[(size_t)(n0 + n) * K + k0 + tx] = __float2half_rn(t[tx][n]);
    }
}

// ---------------------------------------------------------------------------
// RoPE for Q -> scaled fp16
// ---------------------------------------------------------------------------
__global__ void rope_q_kernel(const float* __restrict__ qkv,
                              const int* __restrict__ positions,
                              __half* __restrict__ Qh)
{
    int idx = blockIdx.x * blockDim.x + threadIdx.x;
    int i  = idx & 63;
    int h  = (idx >> 6) & 31;
    int bs = idx >> 11;
    if (bs >= BSc) return;

    const float* src = qkv + (size_t)bs * QKVF + h * Dc;
    float x1 = src[i], x2 = src[i + 64];
    float pos = (float)positions[bs];
    float inv = 1.0f / powf(10000.0f, (float)i * (1.0f / 64.0f));
    float ang = pos * inv;
    float sn, cs;
    sincosf(ang, &sn, &cs);

    size_t o = (size_t)bs * (Hc * Dc) + h * Dc;
    Qh[o + i]      = __float2half_rn((x1 * cs - x2 * sn) * SCF);
    Qh[o + i + 64] = __float2half_rn((x2 * cs + x1 * sn) * SCF);
}

// ---------------------------------------------------------------------------
// Smooth conv + RoPE for K -> scaled fp16
// ---------------------------------------------------------------------------
__global__ void smooth_rope_k_kernel(const float* __restrict__ qkv,
                                     const int* __restrict__ positions,
                                     const float* __restrict__ conv_k,
                                     __half* __restrict__ Kh)
{
    int idx = blockIdx.x * blockDim.x + threadIdx.x;
    int i  = idx & 63;
    int kv = (idx >> 6) & 7;
    int bs = idx >> 9;
    if (bs >= BSc) return;
    int s = bs & (Sc - 1);

    const float* src = qkv + (size_t)bs * QKVF + Hc * Dc + kv * Dc;
    float c1 = src[i], c2 = src[i + 64];
    float p1 = 0.f, p2 = 0.f;
    if (s > 0) {
        const float* ps = src - QKVF;
        p1 = ps[i]; p2 = ps[i + 64];
    }
    float f0 = conv_k[kv], f1 = conv_k[KVc + kv];
    float x1 = c1 * f1 + p1 * f0;
    float x2 = c2 * f1 + p2 * f0;

    float pos = (float)positions[bs];
    float inv = 1.0f / powf(10000.0f, (float)i * (1.0f / 64.0f));
    float ang = pos * inv;
    float sn, cs;
    sincosf(ang, &sn, &cs);

    size_t o = ((size_t)bs * KVc + kv) * Dc;
    Kh[o + i]      = __float2half_rn((x1 * cs - x2 * sn) * SCF);
    Kh[o + i + 64] = __float2half_rn((x2 * cs + x1 * sn) * SCF);
}

// ---------------------------------------------------------------------------
// Smooth conv for V + transpose -> scaled fp16 Vt [b][kv][d][s]
// ---------------------------------------------------------------------------
__global__ void smooth_v_t_kernel(const float* __restrict__ qkv,
                                  const float* __restrict__ conv_v,
                                  __half* __restrict__ Vth)
{
    __shared__ float t[32][33];
    const int tx = threadIdx.x, ty = threadIdx.y;
    const int s0 = blockIdx.x * 32;
    const int d0 = blockIdx.y * 32;
    const int b  = blockIdx.z >> 3;
    const int kv = blockIdx.z & 7;

    const float f0 = conv_v[kv], f1 = conv_v[KVc + kv];
    const size_t voff = (size_t)(Hc + KVc) * Dc + kv * Dc + d0;

#pragma unroll
    for (int i = 0; i < 4; i++) {
        int sl = ty + i * 8;
        int s = s0 + sl;
        const float* src = qkv + (size_t)(b * Sc + s) * QKVF + voff;
        float cur = src[tx];
        float prv = (s > 0) ? src[tx - QKVF] : 0.f;
        t[sl][tx] = (cur * f1 + prv * f0) * SCF;
    }
    __syncthreads();
#pragma unroll
    for (int i = 0; i < 4; i++) {
        int dl = ty + i * 8;
        size_t o = (((size_t)(b * KVc + kv)) * Dc + d0 + dl) * Sc + s0 + tx;
        Vth[o] = __float2half_rn(t[tx][dl]);
    }
}

// ---------------------------------------------------------------------------
// Register-resident windowed flash attention, pure fp16 operands.
// ---------------------------------------------------------------------------
#define RQK  272
#define RPV  144

#define A_QH   0
#define A_ST0  (A_QH + 128 * RQK)                   // 34816
#define KV_STAGE (64 * RQK + 128 * RPV)             // 35840
#define ST_KH  0
#define ST_VH  (64 * RQK)
#define ATTN_SMEM (A_ST0 + 2 * KV_STAGE)            // 106496

__global__ __launch_bounds__(256)
void attn_mma(const __half* __restrict__ Qh,
              const __half* __restrict__ Kh, const __half* __restrict__ Vth,
              __half* __restrict__ Oh)
{
    extern __shared__ char sm[];
    const uint32_t sb = smem_u32(sm);

    const int tid  = threadIdx.x;
    const int w    = tid >> 5;
    const int lane = tid & 31;
    const int g  = lane >> 2;
    const int tg = lane & 3;

    const int qt = blockIdx.x, h = blockIdx.y, b = blockIdx.z;
    const int q0 = qt * 128;
    const int kvh = h >> 2;
    const float scale_eff = 0.08838834764831845f * INV_SC2;

    const uint32_t bmrow = (lane & 7) + (uint32_t)(lane >> 4) * 8;
    const uint32_t bcol  = ((lane >> 3) & 1) * 16;

    // ---- load Q tile via cp.async ----
    {
        const size_t qbase = ((size_t)(b * Sc + q0) * Hc + h) * Dc;
#pragma unroll
        for (int hh = 0; hh < 8; hh++) {
            int idx = tid + hh * 256;
            int r = idx >> 4, u = idx & 15;
            const size_t go = qbase + (size_t)r * (Hc * Dc) + u * 8;
            cp16(sb + A_QH + r * RQK + u * 16, Qh + go);
        }
    }

    const size_t kbase = ((size_t)b * Sc * KVc + kvh) * Dc;
    const size_t vbase = ((size_t)(b * KVc + kvh)) * Dc * Sc;
    auto load_kv = [&](int kt, int st) {
        const int k0 = kt * 64;
        const uint32_t stb = sb + A_ST0 + st * KV_STAGE;
#pragma unroll
        for (int hh = 0; hh < 4; hh++) {
            int idx = tid + hh * 256;
            int r = idx >> 4, u = idx & 15;
            const size_t go = kbase + (size_t)(k0 + r) * (KVc * Dc) + u * 8;
            cp16(stb + ST_KH + r * RQK + u * 16, Kh + go);
        }
#pragma unroll
        for (int hh = 0; hh < 4; hh++) {
            int idx = tid + hh * 256;
            int d = idx >> 3, u = idx & 7;
            const size_t go = vbase + (size_t)d * Sc + k0 + u * 8;
            cp16(stb + ST_VH + d * RPV + u * 16, Vth + go);
        }
    };

    float m0 = -1e30f, m1 = -1e30f, l0 = 0.f, l1 = 0.f;
    float oacc[16][4];
#pragma unroll
    for (int nt = 0; nt < 16; nt++)
#pragma unroll
        for (int j = 0; j < 4; j++) oacc[nt][j] = 0.f;

    const int qw_lo = q0 + w * 16;
    const int qw_hi = qw_lo + 15;
    const int qi0 = qw_lo + g;
    const int qi1 = qi0 + 8;

    int kt_lo = 2 * qt - 8; if (kt_lo < 0) kt_lo = 0;
    const int kt_hi = 2 * qt + 1;

    load_kv(kt_lo, 0);
    CP_COMMIT();

    uint32_t qfh[8][4];

    for (int kt = kt_lo; kt <= kt_hi; kt++) {
        const int st = (kt - kt_lo) & 1;
        const int k0 = kt * 64;
        CP_WAIT0();
        __syncthreads();

        if (kt == kt_lo) {
            const uint32_t amrow = (lane & 7) + ((lane >> 3) & 1) * 8;
            const uint32_t acol  = (uint32_t)(lane >> 4) * 16;
#pragma unroll
            for (int ks = 0; ks < 8; ks++) {
                const uint32_t ar = (uint32_t)((w * 16 + amrow) * RQK) +
                                    (uint32_t)(ks * 32) + acol;
                ldsm_x4(qfh[ks], sb + A_QH + ar);
            }
        }

        if (kt < kt_hi) {
            load_kv(kt + 1, st ^ 1);
            CP_COMMIT();
        }

        if (k0 > qw_hi) continue;
        if (k0 + 575 <= qw_lo) continue;

        const uint32_t stb = sb + A_ST0 + st * KV_STAGE;
        const uint32_t khb = stb + ST_KH;
        const uint32_t vhb = stb + ST_VH;

        // ---- scores (1-term fp16) ----
        float sacc[8][4];
#pragma unroll
        for (int nt = 0; nt < 8; nt++)
#pragma unroll
            for (int j = 0; j < 4; j++) sacc[nt][j] = 0.f;

#pragma unroll
        for (int ks = 0; ks < 8; ks++) {
#pragma unroll
            for (int ntp = 0; ntp < 4; ntp++) {
                const uint32_t br = khb + (uint32_t)((ntp * 16 + bmrow) * RQK) +
                                    (uint32_t)(ks * 32) + bcol;
                uint32_t kh4[4];
                ldsm_x4(kh4, br);
                mma16816(sacc[2 * ntp],     qfh[ks], &kh4[0]);
                mma16816(sacc[2 * ntp + 1], qfh[ks], &kh4[2]);
            }
        }

        // ---- scale + mask ----
        const bool fully_valid = (k0 + 63 <= qw_lo) && (k0 >= qw_hi - (Wc - 1));
        if (fully_valid) {
#pragma unroll
            for (int nt = 0; nt < 8; nt++)
#pragma unroll
                for (int j = 0; j < 4; j++) sacc[nt][j] *= scale_eff;
        } else {
#pragma unroll
            for (int nt = 0; nt < 8; nt++) {
                const int ki0 = k0 + nt * 8 + tg * 2, ki1 = ki0 + 1;
                bool m00 = (ki0 <= qi0) && (qi0 - ki0 < Wc);
                bool m01 = (ki1 <= qi0) && (qi0 - ki1 < Wc);
                bool m10 = (ki0 <= qi1) && (qi1 - ki0 < Wc);
                bool m11 = (ki1 <= qi1) && (qi1 - ki1 < Wc);
                sacc[nt][0] = m00 ? sacc[nt][0] * scale_eff : -1e30f;
                sacc[nt][1] = m01 ? sacc[nt][1] * scale_eff : -1e30f;
                sacc[nt][2] = m10 ? sacc[nt][2] * scale_eff : -1e30f;
                sacc[nt][3] = m11 ? sacc[nt][3] * scale_eff : -1e30f;
            }
        }

        // ---- row max via shfl ----
        float mx0 = -1e30f, mx1 = -1e30f;
#pragma unroll
        for (int nt = 0; nt < 8; nt++) {
            mx0 = fmaxf(mx0, fmaxf(sacc[nt][0], sacc[nt][1]));
            mx1 = fmaxf(mx1, fmaxf(sacc[nt][2], sacc[nt][3]));
        }
        mx0 = fmaxf(mx0, __shfl_xor_sync(0xffffffffu, mx0, 1));
        mx0 = fmaxf(mx0, __shfl_xor_sync(0xffffffffu, mx0, 2));
        mx1 = fmaxf(mx1, __shfl_xor_sync(0xffffffffu, mx1, 1));
        mx1 = fmaxf(mx1, __shfl_xor_sync(0xffffffffu, mx1, 2));

        const float mn0 = fmaxf(m0, mx0);
        const float mn1 = fmaxf(m1, mx1);
        const float f0 = __expf(m0 - mn0);
        const float f1 = __expf(m1 - mn1);
        m0 = mn0; m1 = mn1;

        // ---- exp + sums ----
        float s0 = 0.f, s1 = 0.f;
#pragma unroll
        for (int nt = 0; nt < 8; nt++) {
            float p0 = (sacc[nt][0] > -1e29f) ? __expf(sacc[nt][0] - mn0) : 0.f;
            float p1 = (sacc[nt][1] > -1e29f) ? __expf(sacc[nt][1] - mn0) : 0.f;
            float p2 = (sacc[nt][2] > -1e29f) ? __expf(sacc[nt][2] - mn1) : 0.f;
            float p3 = (sacc[nt][3] > -1e29f) ? __expf(sacc[nt][3] - mn1) : 0.f;
            sacc[nt][0] = p0; sacc[nt][1] = p1; sacc[nt][2] = p2; sacc[nt][3] = p3;
            s0 += p0 + p1; s1 += p2 + p3;
        }
        s0 += __shfl_xor_sync(0xffffffffu, s0, 1);
        s0 += __shfl_xor_sync(0xffffffffu, s0, 2);
        s1 += __shfl_xor_sync(0xffffffffu, s1, 1);
        s1 += __shfl_xor_sync(0xffffffffu, s1, 2);
        l0 = l0 * f0 + s0;
        l1 = l1 * f1 + s1;

#pragma unroll
        for (int nt = 0; nt < 16; nt++) {
            oacc[nt][0] *= f0; oacc[nt][1] *= f0;
            oacc[nt][2] *= f1; oacc[nt][3] *= f1;
        }

        // ---- PV (1-term fp16; P scaled to SCF) ----
#pragma unroll
        for (int ks = 0; ks < 4; ks++) {
            uint32_t aph[4];
            aph[0] = packh2(sacc[2 * ks][0] * SCF,     sacc[2 * ks][1] * SCF);
            aph[1] = packh2(sacc[2 * ks][2] * SCF,     sacc[2 * ks][3] * SCF);
            aph[2] = packh2(sacc[2 * ks + 1][0] * SCF, sacc[2 * ks + 1][1] * SCF);
            aph[3] = packh2(sacc[2 * ks + 1][2] * SCF, sacc[2 * ks + 1][3] * SCF);
#pragma unroll
            for (int ntp = 0; ntp < 8; ntp++) {
                const uint32_t br = vhb + (uint32_t)((ntp * 16 + bmrow) * RPV) +
                                    (uint32_t)(ks * 32) + bcol;
                uint32_t vh4[4];
                ldsm_x4(vh4, br);
                mma16816(oacc[2 * ntp],     aph, &vh4[0]);
                mma16816(oacc[2 * ntp + 1], aph, &vh4[2]);
            }
        }
    }

    // ---- epilogue: normalize, rescale to fp16 GEMM2 A operand ----
    {
        const float linv0 = (1.0f / l0) * (1.0f / SCF);
        const float linv1 = (1.0f / l1) * (1.0f / SCF);
        const size_t tok0 = (size_t)(b * Sc + qw_lo + g);
        const size_t tok1 = tok0 + 8;
#pragma unroll
        for (int nt = 0; nt < 16; nt++) {
            const int col = h * Dc + nt * 8 + tg * 2;
            ((uint32_t*)Oh)[(tok0 * HIDc + col) >> 1] =
                packh2(oacc[nt][0] * linv0, oacc[nt][1] * linv0);
            ((uint32_t*)Oh)[(tok1 * HIDc + col) >> 1] =
                packh2(oacc[nt][2] * linv1, oacc[nt][3] * linv1);
        }
    }
}

// ---------------------------------------------------------------------------
// Launch
// ---------------------------------------------------------------------------
extern "C" void kernel_launch(void* const* d_in, const int* in_sizes, int n_in,
                              void* d_out, int out_size)
{
    const float* hidden    = (const float*)d_in[0];
    const int*   positions = (const int*)d_in[1];
    const float* w_pack    = (const float*)d_in[2];
    const float* w_o       = (const float*)d_in[3];
    const float* conv_k    = (const float*)d_in[4];
    const float* conv_v    = (const float*)d_in[5];
    float* out = (float*)d_out;

    float* qkv;
    __half *qh, *kh, *vth, *ah, *bh;
    cudaGetSymbolAddress((void**)&qkv, g_qkv);
    cudaGetSymbolAddress((void**)&qh,  g_qh);
    cudaGetSymbolAddress((void**)&kh,  g_kh);
    cudaGetSymbolAddress((void**)&vth, g_vth);
    cudaGetSymbolAddress((void**)&ah,  g_ah);
    cudaGetSymbolAddress((void**)&bh,  g_bh);

    cudaFuncSetAttribute(gemm_mma, cudaFuncAttributeMaxDynamicSharedMemorySize,
                         GEMM_SMEM);
    cudaFuncSetAttribute(attn_mma, cudaFuncAttributeMaxDynamicSharedMemorySize,
                         ATTN_SMEM);

    // ---- GEMM 1: qkv = hidden @ w_pack ----
    {
        int n4 = BSc * HIDc / 4;
        conv_a_kernel<<<(n4 + 255) / 256, 256>>>(hidden, ah, n4);
        conv_bt_kernel<<<dim3(QKVF / 32, HIDc / 32), dim3(32, 8)>>>(w_pack, bh, HIDc, QKVF);
        dim3 g1(QKVF / 128, BSc / 128);
        gemm_mma<<<g1, 256, GEMM_SMEM>>>(ah, bh, qkv, BSc, QKVF, HIDc);
    }

    // ---- elementwise prep (emit scaled fp16 operands) ----
    rope_q_kernel<<<(BSc * Hc * 64) / 256, 256>>>(qkv, positions, qh);
    smooth_rope_k_kernel<<<(BSc * KVc * 64) / 256, 256>>>(qkv, positions, conv_k, kh);
    smooth_v_t_kernel<<<dim3(Sc / 32, Dc / 32, Bc * KVc), dim3(32, 8)>>>(qkv, conv_v, vth);

    // prep GEMM2 weights
    conv_bt_kernel<<<dim3(HIDc / 32, HIDc / 32), dim3(32, 8)>>>(w_o, bh, HIDc, HIDc);

    // ---- windowed attention; writes fp16 A for GEMM2 ----
    attn_mma<<<dim3(Sc / 128, Hc, Bc), 256, ATTN_SMEM>>>(qh, kh, vth, ah);

    // ---- GEMM 2: out = attn @ w_o ----
    {
        dim3 g2(HIDc / 128, BSc / 128);
        gemm_mma<<<g2, 256, GEMM_SMEM>>>(ah, bh, out, BSc, HIDc, HIDc);
    }
}

// round 12
// speedup vs baseline: 1.8345x; 1.0009x over previous
#include <cuda_runtime.h>
#include <cuda_fp16.h>
#include <math.h>
#include <stdint.h>

// ---------------------------------------------------------------------------
// Problem constants
// ---------------------------------------------------------------------------
#define Bc    2
#define Sc    2048
#define HIDc  4096
#define Hc    32
#define KVc   8
#define Dc    128
#define Wc    512
#define BSc   (Bc * Sc)              // 4096
#define QKVF  ((Hc + 2 * KVc) * Dc)  // 6144

// global operand scale 2^10
#define SCF      1024.0f
#define INV_SC2  (1.0f / (SCF * SCF))
#define LOG2E    1.4426950408889634f

// ---------------------------------------------------------------------------
// Scratch (static device globals -- no allocation allowed)
// ---------------------------------------------------------------------------
__device__ float g_qkv[(size_t)BSc * QKVF];

__device__ __half g_qh[(size_t)BSc * Hc * Dc];           // roped Q [bs][h][d]
__device__ __half g_kh[(size_t)BSc * KVc * Dc];          // K [bs][kv][d]
__device__ __half g_vh[(size_t)BSc * KVc * Dc];          // V [bs][kv][d]

__device__ __half g_ah[(size_t)BSc * HIDc];              // GEMM A [M,K]
__device__ __half g_bh[(size_t)QKVF * HIDc];             // GEMM B [K,N] (!)

// ---------------------------------------------------------------------------
// Helpers
// ---------------------------------------------------------------------------
__device__ __forceinline__ uint32_t smem_u32(const void* p) {
    uint32_t a;
    asm("{ .reg .u64 t; cvta.to.shared.u64 t, %1; cvt.u32.u64 %0, t; }"
        : "=r"(a) : "l"(p));
    return a;
}
__device__ __forceinline__ void cp16(uint32_t smem, const void* gmem) {
    asm volatile("cp.async.cg.shared.global [%0], [%1], 16;"
                 :: "r"(smem), "l"(gmem));
}
#define CP_COMMIT() asm volatile("cp.async.commit_group;" ::: "memory")
#define CP_WAIT0()  asm volatile("cp.async.wait_group 0;" ::: "memory")

__device__ __forceinline__ void ldsm_x4(uint32_t* r, uint32_t addr) {
    asm volatile("ldmatrix.sync.aligned.m8n8.x4.shared.b16 {%0,%1,%2,%3}, [%4];"
                 : "=r"(r[0]), "=r"(r[1]), "=r"(r[2]), "=r"(r[3]) : "r"(addr));
}
__device__ __forceinline__ void ldsm_x4_t(uint32_t* r, uint32_t addr) {
    asm volatile("ldmatrix.sync.aligned.m8n8.x4.trans.shared.b16 {%0,%1,%2,%3}, [%4];"
                 : "=r"(r[0]), "=r"(r[1]), "=r"(r[2]), "=r"(r[3]) : "r"(addr));
}

// fp16 HMMA m16n8k16, fp32 accumulate
__device__ __forceinline__ void mma16816(float* d, const uint32_t* a,
                                         const uint32_t* b) {
    asm volatile(
        "mma.sync.aligned.m16n8k16.row.col.f32.f16.f16.f32 "
        "{%0,%1,%2,%3}, {%4,%5,%6,%7}, {%8,%9}, {%0,%1,%2,%3};"
        : "+f"(d[0]), "+f"(d[1]), "+f"(d[2]), "+f"(d[3])
        : "r"(a[0]), "r"(a[1]), "r"(a[2]), "r"(a[3]),
          "r"(b[0]), "r"(b[1]));
}

__device__ __forceinline__ uint32_t packh2(float x, float y) {
    __half2 h(__float2half_rn(x), __float2half_rn(y));
    return *(uint32_t*)&h;
}

// ---------------------------------------------------------------------------
// fp16 HMMA GEMM:  C[M,N] = A[M,K] * B[K,N] / SC^2
// A [M,K] fp16; B [K,N] fp16 (loaded with ldmatrix.trans). 2 CTAs/SM, BK=64.
// ---------------------------------------------------------------------------
#define GBK    64
#define AROW   144                          // A smem row stride bytes (64 h + pad)
#define BROW   272                          // B smem row stride bytes (128 h + pad)
#define MAT_A  (128 * AROW)                 // 18432 B
#define MAT_B  (64 * BROW)                  // 17408 B
#define STAGEB (MAT_A + MAT_B)              // 35840 B
#define GEMM_SMEM (2 * STAGEB)              // 71680 B

__global__ __launch_bounds__(256, 2)
void gemm_mma(const __half* __restrict__ Ah,
              const __half* __restrict__ Bh,
              float* __restrict__ C, int M, int N, int K)
{
    extern __shared__ char sm[];
    const uint32_t sb = smem_u32(sm);
    const int tid  = threadIdx.x;
    const int wid  = tid >> 5;
    const int lane = tid & 31;
    const int wm = wid & 3;
    const int wn = wid >> 2;
    const int g  = lane >> 2;
    const int tg = lane & 3;

    const int m0 = blockIdx.y * 128;
    const int n0 = blockIdx.x * 128;

    const uint32_t amrow = (lane & 7) + ((lane >> 3) & 1) * 8;
    const uint32_t acol  = (uint32_t)(lane >> 4) * 16;
    // B (trans): lane rows follow k, hi-16 lanes take next 16B of n
    const uint32_t bkrow = (lane & 7) + ((lane >> 3) & 1) * 8;
    const uint32_t bncol = (uint32_t)(lane >> 4) * 16;

    auto load_stage = [&](int k0, int st) {
        const uint32_t base = sb + st * STAGEB;
        // A: 128 rows x 8 units (128B of k)
#pragma unroll
        for (int hh = 0; hh < 4; hh++) {
            int unit = tid + hh * 256;
            int r = unit >> 3, u = unit & 7;
            const void* gp = Ah + (size_t)(m0 + r) * K + k0 + u * 8;
            cp16(base + r * AROW + u * 16, gp);
        }
        // B: 64 k-rows x 16 units (256B of n)
#pragma unroll
        for (int hh = 0; hh < 4; hh++) {
            int unit = tid + hh * 256;
            int r = unit >> 4, u = unit & 15;
            const void* gp = Bh + (size_t)(k0 + r) * N + n0 + u * 8;
            cp16(base + MAT_A + r * BROW + u * 16, gp);
        }
    };

    float acc[2][8][4];
#pragma unroll
    for (int mt = 0; mt < 2; mt++)
#pragma unroll
        for (int nt = 0; nt < 8; nt++)
#pragma unroll
            for (int j = 0; j < 4; j++) acc[mt][nt][j] = 0.f;

    const int NIT = K / GBK;
    load_stage(0, 0);
    CP_COMMIT();

    for (int it = 0; it < NIT; it++) {
        CP_WAIT0();
        __syncthreads();
        const int st = it & 1;
        if (it + 1 < NIT) {
            load_stage((it + 1) * GBK, st ^ 1);
            CP_COMMIT();
        }

        const uint32_t ahb = sb + st * STAGEB;
        const uint32_t bhb = ahb + MAT_A;

#pragma unroll
        for (int ks = 0; ks < 4; ks++) {
            uint32_t ah[2][4];
#pragma unroll
            for (int mt = 0; mt < 2; mt++) {
                const uint32_t ar = ahb +
                    (uint32_t)((wm * 32 + mt * 16 + amrow) * AROW) +
                    (uint32_t)(ks * 32) + acol;
                ldsm_x4(ah[mt], ar);
            }
#pragma unroll
            for (int ntp = 0; ntp < 4; ntp++) {
                const uint32_t br = bhb +
                    (uint32_t)((ks * 16 + bkrow) * BROW) +
                    (uint32_t)((wn * 64 + ntp * 16) * 2) + bncol;
                uint32_t bh4[4];
                ldsm_x4_t(bh4, br);
#pragma unroll
                for (int mt = 0; mt < 2; mt++) {
                    mma16816(acc[mt][2 * ntp],     ah[mt], &bh4[0]);
                    mma16816(acc[mt][2 * ntp + 1], ah[mt], &bh4[2]);
                }
            }
        }
    }

#pragma unroll
    for (int mt = 0; mt < 2; mt++) {
        const int r0 = m0 + wm * 32 + mt * 16 + g;
#pragma unroll
        for (int nt = 0; nt < 8; nt++) {
            const int cc = n0 + wn * 64 + nt * 8 + tg * 2;
            float2 w0 = make_float2(acc[mt][nt][0] * INV_SC2,
                                    acc[mt][nt][1] * INV_SC2);
            float2 w1 = make_float2(acc[mt][nt][2] * INV_SC2,
                                    acc[mt][nt][3] * INV_SC2);
            *(float2*)(C + (size_t)r0 * N + cc)       = w0;
            *(float2*)(C + (size_t)(r0 + 8) * N + cc) = w1;
        }
    }
}

// ---------------------------------------------------------------------------
// Elementwise fp32 -> scaled fp16 (A operand and B weights; no transpose)
// ---------------------------------------------------------------------------
__global__ void conv_h_kernel(const float* __restrict__ X,
                              __half* __restrict__ Xh, int n4)
{
    int i = blockIdx.x * blockDim.x + threadIdx.x;
    if (i >= n4) return;
    float4 v = ((const float4*)X)[i];
    ((uint32_t*)Xh)[i * 2 + 0] = packh2(v.x * SCF, v.y * SCF);
    ((uint32_t*)Xh)[i * 2 + 1] = packh2(v.z * SCF, v.w * SCF);
}

// ---------------------------------------------------------------------------
// RoPE for Q -> scaled fp16 (exp2-based inv_freq)
// ---------------------------------------------------------------------------
__global__ void rope_q_kernel(const float* __restrict__ qkv,
                              const int* __restrict__ positions,
                              __half* __restrict__ Qh)
{
    int idx = blockIdx.x * blockDim.x + threadIdx.x;
    int i  = idx & 63;
    int h  = (idx >> 6) & 31;
    int bs = idx >> 11;
    if (bs >= BSc) return;

    const float* src = qkv + (size_t)bs * QKVF + h * Dc;
    float x1 = src[i], x2 = src[i + 64];
    float pos = (float)positions[bs];
    float inv = exp2f((float)i * -0.2076205059304601f);   // 10000^(-i/64)
    float ang = pos * inv;
    float sn, cs;
    sincosf(ang, &sn, &cs);

    size_t o = (size_t)bs * (Hc * Dc) + h * Dc;
    Qh[o + i]      = __float2half_rn((x1 * cs - x2 * sn) * SCF);
    Qh[o + i + 64] = __float2half_rn((x2 * cs + x1 * sn) * SCF);
}

// ---------------------------------------------------------------------------
// Smooth conv + RoPE for K -> scaled fp16
// ---------------------------------------------------------------------------
__global__ void smooth_rope_k_kernel(const float* __restrict__ qkv,
                                     const int* __restrict__ positions,
                                     const float* __restrict__ conv_k,
                                     __half* __restrict__ Kh)
{
    int idx = blockIdx.x * blockDim.x + threadIdx.x;
    int i  = idx & 63;
    int kv = (idx >> 6) & 7;
    int bs = idx >> 9;
    if (bs >= BSc) return;
    int s = bs & (Sc - 1);

    const float* src = qkv + (size_t)bs * QKVF + Hc * Dc + kv * Dc;
    float c1 = src[i], c2 = src[i + 64];
    float p1 = 0.f, p2 = 0.f;
    if (s > 0) {
        const float* ps = src - QKVF;
        p1 = ps[i]; p2 = ps[i + 64];
    }
    float f0 = conv_k[kv], f1 = conv_k[KVc + kv];
    float x1 = c1 * f1 + p1 * f0;
    float x2 = c2 * f1 + p2 * f0;

    float pos = (float)positions[bs];
    float inv = exp2f((float)i * -0.2076205059304601f);
    float ang = pos * inv;
    float sn, cs;
    sincosf(ang, &sn, &cs);

    size_t o = ((size_t)bs * KVc + kv) * Dc;
    Kh[o + i]      = __float2half_rn((x1 * cs - x2 * sn) * SCF);
    Kh[o + i + 64] = __float2half_rn((x2 * cs + x1 * sn) * SCF);
}

// ---------------------------------------------------------------------------
// Smooth conv for V -> scaled fp16 [bs][kv][d] (no transpose; elementwise)
// ---------------------------------------------------------------------------
__global__ void smooth_v_kernel(const float* __restrict__ qkv,
                                const float* __restrict__ conv_v,
                                __half* __restrict__ Vh)
{
    int idx = blockIdx.x * blockDim.x + threadIdx.x;   // BS*KV*128
    int d  = idx & 127;
    int kv = (idx >> 7) & 7;
    int bs = idx >> 10;
    if (bs >= BSc) return;
    int s = bs & (Sc - 1);

    const float* src = qkv + (size_t)bs * QKVF + (Hc + KVc) * Dc + kv * Dc;
    float c = src[d];
    float p = (s > 0) ? src[d - QKVF] : 0.f;
    float f0 = conv_v[kv], f1 = conv_v[KVc + kv];
    Vh[((size_t)bs * KVc + kv) * Dc + d] =
        __float2half_rn((c * f1 + p * f0) * SCF);
}

// ---------------------------------------------------------------------------
// Register-resident windowed flash attention, fp16, ldsm.trans for V.
// ---------------------------------------------------------------------------
#define RQK  272                 // Q/K/V smem row stride bytes (128 h + pad)

#define A_QH   0
#define A_ST0  (A_QH + 128 * RQK)                   // 34816
#define KV_STAGE (2 * 64 * RQK)                     // 34816 (K 64 rows + V 64 rows)
#define ST_KH  0
#define ST_VH  (64 * RQK)
#define ATTN_SMEM (A_ST0 + 2 * KV_STAGE)            // 104448

__global__ __launch_bounds__(256)
void attn_mma(const __half* __restrict__ Qh,
              const __half* __restrict__ Kh, const __half* __restrict__ Vh,
              __half* __restrict__ Oh)
{
    extern __shared__ char sm[];
    const uint32_t sb = smem_u32(sm);

    const int tid  = threadIdx.x;
    const int w    = tid >> 5;
    const int lane = tid & 31;
    const int g  = lane >> 2;
    const int tg = lane & 3;

    const int qt = blockIdx.x, h = blockIdx.y, b = blockIdx.z;
    const int q0 = qt * 128;
    const int kvh = h >> 2;
    // log2e folded in: softmax computed base-2
    const float scale_eff = 0.08838834764831845f * INV_SC2 * LOG2E;

    const uint32_t bmrow = (lane & 7) + (uint32_t)(lane >> 4) * 8;   // K (non-trans)
    const uint32_t bcol  = ((lane >> 3) & 1) * 16;
    const uint32_t vkrow = (lane & 7) + ((lane >> 3) & 1) * 8;       // V (trans)
    const uint32_t vncol = (uint32_t)(lane >> 4) * 16;

    // ---- load Q tile via cp.async ----
    {
        const size_t qbase = ((size_t)(b * Sc + q0) * Hc + h) * Dc;
#pragma unroll
        for (int hh = 0; hh < 8; hh++) {
            int idx = tid + hh * 256;
            int r = idx >> 4, u = idx & 15;
            const size_t go = qbase + (size_t)r * (Hc * Dc) + u * 8;
            cp16(sb + A_QH + r * RQK + u * 16, Qh + go);
        }
    }

    const size_t kvbase = ((size_t)b * Sc * KVc + kvh) * Dc;
    auto load_kv = [&](int kt, int st) {
        const int k0 = kt * 64;
        const uint32_t stb = sb + A_ST0 + st * KV_STAGE;
#pragma unroll
        for (int hh = 0; hh < 4; hh++) {
            int idx = tid + hh * 256;
            int r = idx >> 4, u = idx & 15;
            const size_t go = kvbase + (size_t)(k0 + r) * (KVc * Dc) + u * 8;
            cp16(stb + ST_KH + r * RQK + u * 16, Kh + go);
            cp16(stb + ST_VH + r * RQK + u * 16, Vh + go);
        }
    };

    float m0 = -1e30f, m1 = -1e30f, l0 = 0.f, l1 = 0.f;
    float oacc[16][4];
#pragma unroll
    for (int nt = 0; nt < 16; nt++)
#pragma unroll
        for (int j = 0; j < 4; j++) oacc[nt][j] = 0.f;

    const int qw_lo = q0 + w * 16;
    const int qw_hi = qw_lo + 15;
    const int qi0 = qw_lo + g;
    const int qi1 = qi0 + 8;

    int kt_lo = 2 * qt - 8; if (kt_lo < 0) kt_lo = 0;
    const int kt_hi = 2 * qt + 1;

    load_kv(kt_lo, 0);
    CP_COMMIT();

    uint32_t qfh[8][4];

    for (int kt = kt_lo; kt <= kt_hi; kt++) {
        const int st = (kt - kt_lo) & 1;
        const int k0 = kt * 64;
        CP_WAIT0();
        __syncthreads();

        if (kt == kt_lo) {
            const uint32_t amrow = (lane & 7) + ((lane >> 3) & 1) * 8;
            const uint32_t acol  = (uint32_t)(lane >> 4) * 16;
#pragma unroll
            for (int ks = 0; ks < 8; ks++) {
                const uint32_t ar = (uint32_t)((w * 16 + amrow) * RQK) +
                                    (uint32_t)(ks * 32) + acol;
                ldsm_x4(qfh[ks], sb + A_QH + ar);
            }
        }

        if (kt < kt_hi) {
            load_kv(kt + 1, st ^ 1);
            CP_COMMIT();
        }

        if (k0 > qw_hi) continue;
        if (k0 + 575 <= qw_lo) continue;

        const uint32_t stb = sb + A_ST0 + st * KV_STAGE;
        const uint32_t khb = stb + ST_KH;
        const uint32_t vhb = stb + ST_VH;

        // ---- scores ----
        float sacc[8][4];
#pragma unroll
        for (int nt = 0; nt < 8; nt++)
#pragma unroll
            for (int j = 0; j < 4; j++) sacc[nt][j] = 0.f;

#pragma unroll
        for (int ks = 0; ks < 8; ks++) {
#pragma unroll
            for (int ntp = 0; ntp < 4; ntp++) {
                const uint32_t br = khb + (uint32_t)((ntp * 16 + bmrow) * RQK) +
                                    (uint32_t)(ks * 32) + bcol;
                uint32_t kh4[4];
                ldsm_x4(kh4, br);
                mma16816(sacc[2 * ntp],     qfh[ks], &kh4[0]);
                mma16816(sacc[2 * ntp + 1], qfh[ks], &kh4[2]);
            }
        }

        // ---- scale (into log2 domain) + mask ----
        const bool fully_valid = (k0 + 63 <= qw_lo) && (k0 >= qw_hi - (Wc - 1));
        if (fully_valid) {
#pragma unroll
            for (int nt = 0; nt < 8; nt++)
#pragma unroll
                for (int j = 0; j < 4; j++) sacc[nt][j] *= scale_eff;
        } else {
#pragma unroll
            for (int nt = 0; nt < 8; nt++) {
                const int ki0 = k0 + nt * 8 + tg * 2, ki1 = ki0 + 1;
                bool m00 = (ki0 <= qi0) && (qi0 - ki0 < Wc);
                bool m01 = (ki1 <= qi0) && (qi0 - ki1 < Wc);
                bool m10 = (ki0 <= qi1) && (qi1 - ki0 < Wc);
                bool m11 = (ki1 <= qi1) && (qi1 - ki1 < Wc);
                sacc[nt][0] = m00 ? sacc[nt][0] * scale_eff : -1e30f;
                sacc[nt][1] = m01 ? sacc[nt][1] * scale_eff : -1e30f;
                sacc[nt][2] = m10 ? sacc[nt][2] * scale_eff : -1e30f;
                sacc[nt][3] = m11 ? sacc[nt][3] * scale_eff : -1e30f;
            }
        }

        // ---- row max via shfl ----
        float mx0 = -1e30f, mx1 = -1e30f;
#pragma unroll
        for (int nt = 0; nt < 8; nt++) {
            mx0 = fmaxf(mx0, fmaxf(sacc[nt][0], sacc[nt][1]));
            mx1 = fmaxf(mx1, fmaxf(sacc[nt][2], sacc[nt][3]));
        }
        mx0 = fmaxf(mx0, __shfl_xor_sync(0xffffffffu, mx0, 1));
        mx0 = fmaxf(mx0, __shfl_xor_sync(0xffffffffu, mx0, 2));
        mx1 = fmaxf(mx1, __shfl_xor_sync(0xffffffffu, mx1, 1));
        mx1 = fmaxf(mx1, __shfl_xor_sync(0xffffffffu, mx1, 2));

        const float mn0 = fmaxf(m0, mx0);
        const float mn1 = fmaxf(m1, mx1);
        const float f0 = exp2f(m0 - mn0);
        const float f1 = exp2f(m1 - mn1);
        m0 = mn0; m1 = mn1;

        // ---- exp2 + sums ----
        float s0 = 0.f, s1 = 0.f;
#pragma unroll
        for (int nt = 0; nt < 8; nt++) {
            float p0 = (sacc[nt][0] > -1e29f) ? exp2f(sacc[nt][0] - mn0) : 0.f;
            float p1 = (sacc[nt][1] > -1e29f) ? exp2f(sacc[nt][1] - mn0) : 0.f;
            float p2 = (sacc[nt][2] > -1e29f) ? exp2f(sacc[nt][2] - mn1) : 0.f;
            float p3 = (sacc[nt][3] > -1e29f) ? exp2f(sacc[nt][3] - mn1) : 0.f;
            sacc[nt][0] = p0; sacc[nt][1] = p1; sacc[nt][2] = p2; sacc[nt][3] = p3;
            s0 += p0 + p1; s1 += p2 + p3;
        }
        s0 += __shfl_xor_sync(0xffffffffu, s0, 1);
        s0 += __shfl_xor_sync(0xffffffffu, s0, 2);
        s1 += __shfl_xor_sync(0xffffffffu, s1, 1);
        s1 += __shfl_xor_sync(0xffffffffu, s1, 2);
        l0 = l0 * f0 + s0;
        l1 = l1 * f1 + s1;

#pragma unroll
        for (int nt = 0; nt < 16; nt++) {
            oacc[nt][0] *= f0; oacc[nt][1] *= f0;
            oacc[nt][2] *= f1; oacc[nt][3] *= f1;
        }

        // ---- PV: V fragments via ldsm.trans from [s][d] layout ----
#pragma unroll
        for (int ks = 0; ks < 4; ks++) {
            uint32_t aph[4];
            aph[0] = packh2(sacc[2 * ks][0] * SCF,     sacc[2 * ks][1] * SCF);
            aph[1] = packh2(sacc[2 * ks][2] * SCF,     sacc[2 * ks][3] * SCF);
            aph[2] = packh2(sacc[2 * ks + 1][0] * SCF, sacc[2 * ks + 1][1] * SCF);
            aph[3] = packh2(sacc[2 * ks + 1][2] * SCF, sacc[2 * ks + 1][3] * SCF);
#pragma unroll
            for (int ntp = 0; ntp < 8; ntp++) {
                const uint32_t br = vhb + (uint32_t)((ks * 16 + vkrow) * RQK) +
                                    (uint32_t)(ntp * 32) + vncol;
                uint32_t vh4[4];
                ldsm_x4_t(vh4, br);
                mma16816(oacc[2 * ntp],     aph, &vh4[0]);
                mma16816(oacc[2 * ntp + 1], aph, &vh4[2]);
            }
        }
    }

    // ---- epilogue: normalize, rescale to fp16 GEMM2 A operand ----
    {
        const float linv0 = (1.0f / l0) * (1.0f / SCF);
        const float linv1 = (1.0f / l1) * (1.0f / SCF);
        const size_t tok0 = (size_t)(b * Sc + qw_lo + g);
        const size_t tok1 = tok0 + 8;
#pragma unroll
        for (int nt = 0; nt < 16; nt++) {
            const int col = h * Dc + nt * 8 + tg * 2;
            ((uint32_t*)Oh)[(tok0 * HIDc + col) >> 1] =
                packh2(oacc[nt][0] * linv0, oacc[nt][1] * linv0);
            ((uint32_t*)Oh)[(tok1 * HIDc + col) >> 1] =
                packh2(oacc[nt][2] * linv1, oacc[nt][3] * linv1);
        }
    }
}

// ---------------------------------------------------------------------------
// Launch
// ---------------------------------------------------------------------------
extern "C" void kernel_launch(void* const* d_in, const int* in_sizes, int n_in,
                              void* d_out, int out_size)
{
    const float* hidden    = (const float*)d_in[0];
    const int*   positions = (const int*)d_in[1];
    const float* w_pack    = (const float*)d_in[2];
    const float* w_o       = (const float*)d_in[3];
    const float* conv_k    = (const float*)d_in[4];
    const float* conv_v    = (const float*)d_in[5];
    float* out = (float*)d_out;

    float* qkv;
    __half *qh, *kh, *vh, *ah, *bh;
    cudaGetSymbolAddress((void**)&qkv, g_qkv);
    cudaGetSymbolAddress((void**)&qh,  g_qh);
    cudaGetSymbolAddress((void**)&kh,  g_kh);
    cudaGetSymbolAddress((void**)&vh,  g_vh);
    cudaGetSymbolAddress((void**)&ah,  g_ah);
    cudaGetSymbolAddress((void**)&bh,  g_bh);

    cudaFuncSetAttribute(gemm_mma, cudaFuncAttributeMaxDynamicSharedMemorySize,
                         GEMM_SMEM);
    cudaFuncSetAttribute(attn_mma, cudaFuncAttributeMaxDynamicSharedMemorySize,
                         ATTN_SMEM);

    // ---- GEMM 1: qkv = hidden @ w_pack ----
    {
        int n4a = BSc * HIDc / 4;
        int n4b = HIDc * QKVF / 4;
        conv_h_kernel<<<(n4a + 255) / 256, 256>>>(hidden, ah, n4a);
        conv_h_kernel<<<(n4b + 255) / 256, 256>>>(w_pack, bh, n4b);
        dim3 g1(QKVF / 128, BSc / 128);
        gemm_mma<<<g1, 256, GEMM_SMEM>>>(ah, bh, qkv, BSc, QKVF, HIDc);
    }

    // ---- elementwise prep (emit scaled fp16 operands) ----
    rope_q_kernel<<<(BSc * Hc * 64) / 256, 256>>>(qkv, positions, qh);
    smooth_rope_k_kernel<<<(BSc * KVc * 64) / 256, 256>>>(qkv, positions, conv_k, kh);
    smooth_v_kernel<<<(BSc * KVc * 128) / 256, 256>>>(qkv, conv_v, vh);

    // prep GEMM2 weights (elementwise convert, no transpose)
    {
        int n4 = HIDc * HIDc / 4;
        conv_h_kernel<<<(n4 + 255) / 256, 256>>>(w_o, bh, n4);
    }

    // ---- windowed attention; writes fp16 A for GEMM2 ----
    attn_mma<<<dim3(Sc / 128, Hc, Bc), 256, ATTN_SMEM>>>(qh, kh, vh, ah);

    // ---- GEMM 2: out = attn @ w_o ----
    {
        dim3 g2(HIDc / 128, BSc / 128);
        gemm_mma<<<g2, 256, GEMM_SMEM>>>(ah, bh, out, BSc, HIDc, HIDc);
    }
}

// round 13
// speedup vs baseline: 1.8604x; 1.0141x over previous
#include <cuda_runtime.h>
#include <cuda_fp16.h>
#include <math.h>
#include <stdint.h>

// ---------------------------------------------------------------------------
// Problem constants
// ---------------------------------------------------------------------------
#define Bc    2
#define Sc    2048
#define HIDc  4096
#define Hc    32
#define KVc   8
#define Dc    128
#define Wc    512
#define BSc   (Bc * Sc)              // 4096
#define QKVF  ((Hc + 2 * KVc) * Dc)  // 6144

// global operand scale 2^10
#define SCF      1024.0f
#define INV_SC2  (1.0f / (SCF * SCF))
#define LOG2E    1.4426950408889634f

// ---------------------------------------------------------------------------
// Scratch (static device globals -- no allocation allowed)
// ---------------------------------------------------------------------------
__device__ float g_qkv[(size_t)BSc * QKVF];

__device__ __half g_qh[(size_t)BSc * Hc * Dc];           // roped Q [bs][h][d]
__device__ __half g_kh[(size_t)BSc * KVc * Dc];          // K [bs][kv][d]
__device__ __half g_vh[(size_t)BSc * KVc * Dc];          // V [bs][kv][d]

__device__ __half g_ah[(size_t)BSc * HIDc];              // GEMM A [M,K]
__device__ __half g_bh[(size_t)QKVF * HIDc];             // GEMM B [K,N]

// ---------------------------------------------------------------------------
// Helpers
// ---------------------------------------------------------------------------
__device__ __forceinline__ uint32_t smem_u32(const void* p) {
    uint32_t a;
    asm("{ .reg .u64 t; cvta.to.shared.u64 t, %1; cvt.u32.u64 %0, t; }"
        : "=r"(a) : "l"(p));
    return a;
}
__device__ __forceinline__ void cp16(uint32_t smem, const void* gmem) {
    asm volatile("cp.async.cg.shared.global [%0], [%1], 16;"
                 :: "r"(smem), "l"(gmem));
}
#define CP_COMMIT() asm volatile("cp.async.commit_group;" ::: "memory")
#define CP_WAIT0()  asm volatile("cp.async.wait_group 0;" ::: "memory")

__device__ __forceinline__ void ldsm_x4(uint32_t* r, uint32_t addr) {
    asm volatile("ldmatrix.sync.aligned.m8n8.x4.shared.b16 {%0,%1,%2,%3}, [%4];"
                 : "=r"(r[0]), "=r"(r[1]), "=r"(r[2]), "=r"(r[3]) : "r"(addr));
}
__device__ __forceinline__ void ldsm_x4_t(uint32_t* r, uint32_t addr) {
    asm volatile("ldmatrix.sync.aligned.m8n8.x4.trans.shared.b16 {%0,%1,%2,%3}, [%4];"
                 : "=r"(r[0]), "=r"(r[1]), "=r"(r[2]), "=r"(r[3]) : "r"(addr));
}

// fp16 HMMA m16n8k16, fp32 accumulate
__device__ __forceinline__ void mma16816(float* d, const uint32_t* a,
                                         const uint32_t* b) {
    asm volatile(
        "mma.sync.aligned.m16n8k16.row.col.f32.f16.f16.f32 "
        "{%0,%1,%2,%3}, {%4,%5,%6,%7}, {%8,%9}, {%0,%1,%2,%3};"
        : "+f"(d[0]), "+f"(d[1]), "+f"(d[2]), "+f"(d[3])
        : "r"(a[0]), "r"(a[1]), "r"(a[2]), "r"(a[3]),
          "r"(b[0]), "r"(b[1]));
}

__device__ __forceinline__ uint32_t packh2(float x, float y) {
    __half2 h(__float2half_rn(x), __float2half_rn(y));
    return *(uint32_t*)&h;
}

// ---------------------------------------------------------------------------
// fp16 HMMA GEMM (unchanged from R12 passing version)
// ---------------------------------------------------------------------------
#define GBK    64
#define AROW   144
#define BROW   272
#define MAT_A  (128 * AROW)
#define MAT_B  (64 * BROW)
#define STAGEB (MAT_A + MAT_B)
#define GEMM_SMEM (2 * STAGEB)

__global__ __launch_bounds__(256, 2)
void gemm_mma(const __half* __restrict__ Ah,
              const __half* __restrict__ Bh,
              float* __restrict__ C, int M, int N, int K)
{
    extern __shared__ char sm[];
    const uint32_t sb = smem_u32(sm);
    const int tid  = threadIdx.x;
    const int wid  = tid >> 5;
    const int lane = tid & 31;
    const int wm = wid & 3;
    const int wn = wid >> 2;
    const int g  = lane >> 2;
    const int tg = lane & 3;

    const int m0 = blockIdx.y * 128;
    const int n0 = blockIdx.x * 128;

    const uint32_t amrow = (lane & 7) + ((lane >> 3) & 1) * 8;
    const uint32_t acol  = (uint32_t)(lane >> 4) * 16;
    const uint32_t bkrow = (lane & 7) + ((lane >> 3) & 1) * 8;
    const uint32_t bncol = (uint32_t)(lane >> 4) * 16;

    auto load_stage = [&](int k0, int st) {
        const uint32_t base = sb + st * STAGEB;
#pragma unroll
        for (int hh = 0; hh < 4; hh++) {
            int unit = tid + hh * 256;
            int r = unit >> 3, u = unit & 7;
            const void* gp = Ah + (size_t)(m0 + r) * K + k0 + u * 8;
            cp16(base + r * AROW + u * 16, gp);
        }
#pragma unroll
        for (int hh = 0; hh < 4; hh++) {
            int unit = tid + hh * 256;
            int r = unit >> 4, u = unit & 15;
            const void* gp = Bh + (size_t)(k0 + r) * N + n0 + u * 8;
            cp16(base + MAT_A + r * BROW + u * 16, gp);
        }
    };

    float acc[2][8][4];
#pragma unroll
    for (int mt = 0; mt < 2; mt++)
#pragma unroll
        for (int nt = 0; nt < 8; nt++)
#pragma unroll
            for (int j = 0; j < 4; j++) acc[mt][nt][j] = 0.f;

    const int NIT = K / GBK;
    load_stage(0, 0);
    CP_COMMIT();

    for (int it = 0; it < NIT; it++) {
        CP_WAIT0();
        __syncthreads();
        const int st = it & 1;
        if (it + 1 < NIT) {
            load_stage((it + 1) * GBK, st ^ 1);
            CP_COMMIT();
        }

        const uint32_t ahb = sb + st * STAGEB;
        const uint32_t bhb = ahb + MAT_A;

#pragma unroll
        for (int ks = 0; ks < 4; ks++) {
            uint32_t ah[2][4];
#pragma unroll
            for (int mt = 0; mt < 2; mt++) {
                const uint32_t ar = ahb +
                    (uint32_t)((wm * 32 + mt * 16 + amrow) * AROW) +
                    (uint32_t)(ks * 32) + acol;
                ldsm_x4(ah[mt], ar);
            }
#pragma unroll
            for (int ntp = 0; ntp < 4; ntp++) {
                const uint32_t br = bhb +
                    (uint32_t)((ks * 16 + bkrow) * BROW) +
                    (uint32_t)((wn * 64 + ntp * 16) * 2) + bncol;
                uint32_t bh4[4];
                ldsm_x4_t(bh4, br);
#pragma unroll
                for (int mt = 0; mt < 2; mt++) {
                    mma16816(acc[mt][2 * ntp],     ah[mt], &bh4[0]);
                    mma16816(acc[mt][2 * ntp + 1], ah[mt], &bh4[2]);
                }
            }
        }
    }

#pragma unroll
    for (int mt = 0; mt < 2; mt++) {
        const int r0 = m0 + wm * 32 + mt * 16 + g;
#pragma unroll
        for (int nt = 0; nt < 8; nt++) {
            const int cc = n0 + wn * 64 + nt * 8 + tg * 2;
            float2 w0 = make_float2(acc[mt][nt][0] * INV_SC2,
                                    acc[mt][nt][1] * INV_SC2);
            float2 w1 = make_float2(acc[mt][nt][2] * INV_SC2,
                                    acc[mt][nt][3] * INV_SC2);
            *(float2*)(C + (size_t)r0 * N + cc)       = w0;
            *(float2*)(C + (size_t)(r0 + 8) * N + cc) = w1;
        }
    }
}

// ---------------------------------------------------------------------------
// Fused input conversion: hidden -> g_ah, w_pack -> g_bh (blockIdx dispatch)
// ---------------------------------------------------------------------------
#define N4_HID  (BSc * HIDc / 4)             // 4,194,304
#define NB_HID  (N4_HID / 256)               // 16384
#define N4_WP   (HIDc * QKVF / 4)            // 6,291,456
#define NB_WP   (N4_WP / 256)                // 24576

__global__ void conv_in_kernel(const float* __restrict__ hidden,
                               const float* __restrict__ w_pack,
                               __half* __restrict__ Ah,
                               __half* __restrict__ Bh)
{
    int bid = blockIdx.x;
    if (bid < NB_HID) {
        int i = bid * 256 + threadIdx.x;
        float4 v = ((const float4*)hidden)[i];
        ((uint32_t*)Ah)[i * 2 + 0] = packh2(v.x * SCF, v.y * SCF);
        ((uint32_t*)Ah)[i * 2 + 1] = packh2(v.z * SCF, v.w * SCF);
    } else {
        int i = (bid - NB_HID) * 256 + threadIdx.x;
        float4 v = ((const float4*)w_pack)[i];
        ((uint32_t*)Bh)[i * 2 + 0] = packh2(v.x * SCF, v.y * SCF);
        ((uint32_t*)Bh)[i * 2 + 1] = packh2(v.z * SCF, v.w * SCF);
    }
}

// ---------------------------------------------------------------------------
// Fused prep: rope_q + smooth_k + smooth_v + w_o conversion (one launch)
// ---------------------------------------------------------------------------
#define NB_Q   (BSc * Hc * 64 / 256)         // 32768
#define NB_K   (BSc * KVc * 64 / 256)        // 8192
#define NB_V   (BSc * KVc * 128 / 256)       // 16384
#define N4_WO  (HIDc * HIDc / 4)             // 4,194,304
#define NB_WO  (N4_WO / 256)                 // 16384

__global__ void fused_prep_kernel(const float* __restrict__ qkv,
                                  const int* __restrict__ positions,
                                  const float* __restrict__ conv_k,
                                  const float* __restrict__ conv_v,
                                  const float* __restrict__ w_o,
                                  __half* __restrict__ Qh,
                                  __half* __restrict__ Kh,
                                  __half* __restrict__ Vh,
                                  __half* __restrict__ Bh)
{
    int bid = blockIdx.x;
    if (bid < NB_Q) {
        // ---- rope Q ----
        int idx = bid * 256 + threadIdx.x;
        int i  = idx & 63;
        int h  = (idx >> 6) & 31;
        int bs = idx >> 11;

        const float* src = qkv + (size_t)bs * QKVF + h * Dc;
        float x1 = src[i], x2 = src[i + 64];
        float pos = (float)positions[bs];
        float inv = exp2f((float)i * -0.2076205059304601f);
        float ang = pos * inv;
        float sn, cs;
        sincosf(ang, &sn, &cs);

        size_t o = (size_t)bs * (Hc * Dc) + h * Dc;
        Qh[o + i]      = __float2half_rn((x1 * cs - x2 * sn) * SCF);
        Qh[o + i + 64] = __float2half_rn((x2 * cs + x1 * sn) * SCF);
    } else if (bid < NB_Q + NB_K) {
        // ---- smooth + rope K ----
        int idx = (bid - NB_Q) * 256 + threadIdx.x;
        int i  = idx & 63;
        int kv = (idx >> 6) & 7;
        int bs = idx >> 9;
        int s = bs & (Sc - 1);

        const float* src = qkv + (size_t)bs * QKVF + Hc * Dc + kv * Dc;
        float c1 = src[i], c2 = src[i + 64];
        float p1 = 0.f, p2 = 0.f;
        if (s > 0) {
            const float* ps = src - QKVF;
            p1 = ps[i]; p2 = ps[i + 64];
        }
        float f0 = conv_k[kv], f1 = conv_k[KVc + kv];
        float x1 = c1 * f1 + p1 * f0;
        float x2 = c2 * f1 + p2 * f0;

        float pos = (float)positions[bs];
        float inv = exp2f((float)i * -0.2076205059304601f);
        float ang = pos * inv;
        float sn, cs;
        sincosf(ang, &sn, &cs);

        size_t o = ((size_t)bs * KVc + kv) * Dc;
        Kh[o + i]      = __float2half_rn((x1 * cs - x2 * sn) * SCF);
        Kh[o + i + 64] = __float2half_rn((x2 * cs + x1 * sn) * SCF);
    } else if (bid < NB_Q + NB_K + NB_V) {
        // ---- smooth V ----
        int idx = (bid - NB_Q - NB_K) * 256 + threadIdx.x;
        int d  = idx & 127;
        int kv = (idx >> 7) & 7;
        int bs = idx >> 10;
        int s = bs & (Sc - 1);

        const float* src = qkv + (size_t)bs * QKVF + (Hc + KVc) * Dc + kv * Dc;
        float c = src[d];
        float p = (s > 0) ? src[d - QKVF] : 0.f;
        float f0 = conv_v[kv], f1 = conv_v[KVc + kv];
        Vh[((size_t)bs * KVc + kv) * Dc + d] =
            __float2half_rn((c * f1 + p * f0) * SCF);
    } else {
        // ---- w_o conversion ----
        int i = (bid - NB_Q - NB_K - NB_V) * 256 + threadIdx.x;
        float4 v = ((const float4*)w_o)[i];
        ((uint32_t*)Bh)[i * 2 + 0] = packh2(v.x * SCF, v.y * SCF);
        ((uint32_t*)Bh)[i * 2 + 1] = packh2(v.z * SCF, v.w * SCF);
    }
}

// ---------------------------------------------------------------------------
// Register-resident windowed flash attention, fp16.
// 128-thread CTAs (4 warps, 64 q rows) at 2 CTAs/SM for bubble overlap.
// ---------------------------------------------------------------------------
#define RQK  272

#define A_QH   0
#define A_ST0  (A_QH + 64 * RQK)                    // 17408
#define KV_STAGE (2 * 64 * RQK)                     // 34816
#define ST_KH  0
#define ST_VH  (64 * RQK)
#define ATTN_SMEM (A_ST0 + 2 * KV_STAGE)            // 87040

__global__ __launch_bounds__(128, 2)
void attn_mma(const __half* __restrict__ Qh,
              const __half* __restrict__ Kh, const __half* __restrict__ Vh,
              __half* __restrict__ Oh)
{
    extern __shared__ char sm[];
    const uint32_t sb = smem_u32(sm);

    const int tid  = threadIdx.x;
    const int w    = tid >> 5;           // 0..3
    const int lane = tid & 31;
    const int g  = lane >> 2;
    const int tg = lane & 3;

    const int qt = blockIdx.x, h = blockIdx.y, b = blockIdx.z;
    const int q0 = qt * 64;
    const int kvh = h >> 2;
    const float scale_eff = 0.08838834764831845f * INV_SC2 * LOG2E;

    const uint32_t bmrow = (lane & 7) + (uint32_t)(lane >> 4) * 8;   // K
    const uint32_t bcol  = ((lane >> 3) & 1) * 16;
    const uint32_t vkrow = (lane & 7) + ((lane >> 3) & 1) * 8;       // V (trans)
    const uint32_t vncol = (uint32_t)(lane >> 4) * 16;

    // ---- load Q tile (64 rows) via cp.async ----
    {
        const size_t qbase = ((size_t)(b * Sc + q0) * Hc + h) * Dc;
#pragma unroll
        for (int hh = 0; hh < 8; hh++) {
            int idx = tid + hh * 128;
            int r = idx >> 4, u = idx & 15;
            const size_t go = qbase + (size_t)r * (Hc * Dc) + u * 8;
            cp16(sb + A_QH + r * RQK + u * 16, Qh + go);
        }
    }

    const size_t kvbase = ((size_t)b * Sc * KVc + kvh) * Dc;
    auto load_kv = [&](int kt, int st) {
        const int k0 = kt * 64;
        const uint32_t stb = sb + A_ST0 + st * KV_STAGE;
#pragma unroll
        for (int hh = 0; hh < 8; hh++) {
            int idx = tid + hh * 128;
            int r = idx >> 4, u = idx & 15;
            const size_t go = kvbase + (size_t)(k0 + r) * (KVc * Dc) + u * 8;
            cp16(stb + ST_KH + r * RQK + u * 16, Kh + go);
            cp16(stb + ST_VH + r * RQK + u * 16, Vh + go);
        }
    };

    float m0 = -1e30f, m1 = -1e30f, l0 = 0.f, l1 = 0.f;
    float oacc[16][4];
#pragma unroll
    for (int nt = 0; nt < 16; nt++)
#pragma unroll
        for (int j = 0; j < 4; j++) oacc[nt][j] = 0.f;

    const int qw_lo = q0 + w * 16;
    const int qw_hi = qw_lo + 15;
    const int qi0 = qw_lo + g;
    const int qi1 = qi0 + 8;

    int kt_lo = qt - 8; if (kt_lo < 0) kt_lo = 0;
    const int kt_hi = qt;

    load_kv(kt_lo, 0);
    CP_COMMIT();

    uint32_t qfh[8][4];

    for (int kt = kt_lo; kt <= kt_hi; kt++) {
        const int st = (kt - kt_lo) & 1;
        const int k0 = kt * 64;
        CP_WAIT0();
        __syncthreads();

        if (kt == kt_lo) {
            const uint32_t amrow = (lane & 7) + ((lane >> 3) & 1) * 8;
            const uint32_t acol  = (uint32_t)(lane >> 4) * 16;
#pragma unroll
            for (int ks = 0; ks < 8; ks++) {
                const uint32_t ar = (uint32_t)((w * 16 + amrow) * RQK) +
                                    (uint32_t)(ks * 32) + acol;
                ldsm_x4(qfh[ks], sb + A_QH + ar);
            }
        }

        if (kt < kt_hi) {
            load_kv(kt + 1, st ^ 1);
            CP_COMMIT();
        }

        if (k0 > qw_hi) continue;
        if (k0 + 575 <= qw_lo) continue;

        const uint32_t stb = sb + A_ST0 + st * KV_STAGE;
        const uint32_t khb = stb + ST_KH;
        const uint32_t vhb = stb + ST_VH;

        // ---- scores ----
        float sacc[8][4];
#pragma unroll
        for (int nt = 0; nt < 8; nt++)
#pragma unroll
            for (int j = 0; j < 4; j++) sacc[nt][j] = 0.f;

#pragma unroll
        for (int ks = 0; ks < 8; ks++) {
#pragma unroll
            for (int ntp = 0; ntp < 4; ntp++) {
                const uint32_t br = khb + (uint32_t)((ntp * 16 + bmrow) * RQK) +
                                    (uint32_t)(ks * 32) + bcol;
                uint32_t kh4[4];
                ldsm_x4(kh4, br);
                mma16816(sacc[2 * ntp],     qfh[ks], &kh4[0]);
                mma16816(sacc[2 * ntp + 1], qfh[ks], &kh4[2]);
            }
        }

        // ---- scale (log2 domain) + mask ----
        const bool fully_valid = (k0 + 63 <= qw_lo) && (k0 >= qw_hi - (Wc - 1));
        if (fully_valid) {
#pragma unroll
            for (int nt = 0; nt < 8; nt++)
#pragma unroll
                for (int j = 0; j < 4; j++) sacc[nt][j] *= scale_eff;
        } else {
#pragma unroll
            for (int nt = 0; nt < 8; nt++) {
                const int ki0 = k0 + nt * 8 + tg * 2, ki1 = ki0 + 1;
                bool m00 = (ki0 <= qi0) && (qi0 - ki0 < Wc);
                bool m01 = (ki1 <= qi0) && (qi0 - ki1 < Wc);
                bool m10 = (ki0 <= qi1) && (qi1 - ki0 < Wc);
                bool m11 = (ki1 <= qi1) && (qi1 - ki1 < Wc);
                sacc[nt][0] = m00 ? sacc[nt][0] * scale_eff : -1e30f;
                sacc[nt][1] = m01 ? sacc[nt][1] * scale_eff : -1e30f;
                sacc[nt][2] = m10 ? sacc[nt][2] * scale_eff : -1e30f;
                sacc[nt][3] = m11 ? sacc[nt][3] * scale_eff : -1e30f;
            }
        }

        // ---- row max via shfl ----
        float mx0 = -1e30f, mx1 = -1e30f;
#pragma unroll
        for (int nt = 0; nt < 8; nt++) {
            mx0 = fmaxf(mx0, fmaxf(sacc[nt][0], sacc[nt][1]));
            mx1 = fmaxf(mx1, fmaxf(sacc[nt][2], sacc[nt][3]));
        }
        mx0 = fmaxf(mx0, __shfl_xor_sync(0xffffffffu, mx0, 1));
        mx0 = fmaxf(mx0, __shfl_xor_sync(0xffffffffu, mx0, 2));
        mx1 = fmaxf(mx1, __shfl_xor_sync(0xffffffffu, mx1, 1));
        mx1 = fmaxf(mx1, __shfl_xor_sync(0xffffffffu, mx1, 2));

        const float mn0 = fmaxf(m0, mx0);
        const float mn1 = fmaxf(m1, mx1);
        const float f0 = exp2f(m0 - mn0);
        const float f1 = exp2f(m1 - mn1);
        m0 = mn0; m1 = mn1;

        // ---- exp2 + sums ----
        float s0 = 0.f, s1 = 0.f;
#pragma unroll
        for (int nt = 0; nt < 8; nt++) {
            float p0 = (sacc[nt][0] > -1e29f) ? exp2f(sacc[nt][0] - mn0) : 0.f;
            float p1 = (sacc[nt][1] > -1e29f) ? exp2f(sacc[nt][1] - mn0) : 0.f;
            float p2 = (sacc[nt][2] > -1e29f) ? exp2f(sacc[nt][2] - mn1) : 0.f;
            float p3 = (sacc[nt][3] > -1e29f) ? exp2f(sacc[nt][3] - mn1) : 0.f;
            sacc[nt][0] = p0; sacc[nt][1] = p1; sacc[nt][2] = p2; sacc[nt][3] = p3;
            s0 += p0 + p1; s1 += p2 + p3;
        }
        s0 += __shfl_xor_sync(0xffffffffu, s0, 1);
        s0 += __shfl_xor_sync(0xffffffffu, s0, 2);
        s1 += __shfl_xor_sync(0xffffffffu, s1, 1);
        s1 += __shfl_xor_sync(0xffffffffu, s1, 2);
        l0 = l0 * f0 + s0;
        l1 = l1 * f1 + s1;

#pragma unroll
        for (int nt = 0; nt < 16; nt++) {
            oacc[nt][0] *= f0; oacc[nt][1] *= f0;
            oacc[nt][2] *= f1; oacc[nt][3] *= f1;
        }

        // ---- PV: V fragments via ldsm.trans from [s][d] layout ----
#pragma unroll
        for (int ks = 0; ks < 4; ks++) {
            uint32_t aph[4];
            aph[0] = packh2(sacc[2 * ks][0] * SCF,     sacc[2 * ks][1] * SCF);
            aph[1] = packh2(sacc[2 * ks][2] * SCF,     sacc[2 * ks][3] * SCF);
            aph[2] = packh2(sacc[2 * ks + 1][0] * SCF, sacc[2 * ks + 1][1] * SCF);
            aph[3] = packh2(sacc[2 * ks + 1][2] * SCF, sacc[2 * ks + 1][3] * SCF);
#pragma unroll
            for (int ntp = 0; ntp < 8; ntp++) {
                const uint32_t br = vhb + (uint32_t)((ks * 16 + vkrow) * RQK) +
                                    (uint32_t)(ntp * 32) + vncol;
                uint32_t vh4[4];
                ldsm_x4_t(vh4, br);
                mma16816(oacc[2 * ntp],     aph, &vh4[0]);
                mma16816(oacc[2 * ntp + 1], aph, &vh4[2]);
            }
        }
    }

    // ---- epilogue: normalize, rescale to fp16 GEMM2 A operand ----
    {
        const float linv0 = (1.0f / l0) * (1.0f / SCF);
        const float linv1 = (1.0f / l1) * (1.0f / SCF);
        const size_t tok0 = (size_t)(b * Sc + qw_lo + g);
        const size_t tok1 = tok0 + 8;
#pragma unroll
        for (int nt = 0; nt < 16; nt++) {
            const int col = h * Dc + nt * 8 + tg * 2;
            ((uint32_t*)Oh)[(tok0 * HIDc + col) >> 1] =
                packh2(oacc[nt][0] * linv0, oacc[nt][1] * linv0);
            ((uint32_t*)Oh)[(tok1 * HIDc + col) >> 1] =
                packh2(oacc[nt][2] * linv1, oacc[nt][3] * linv1);
        }
    }
}

// ---------------------------------------------------------------------------
// Launch
// ---------------------------------------------------------------------------
extern "C" void kernel_launch(void* const* d_in, const int* in_sizes, int n_in,
                              void* d_out, int out_size)
{
    const float* hidden    = (const float*)d_in[0];
    const int*   positions = (const int*)d_in[1];
    const float* w_pack    = (const float*)d_in[2];
    const float* w_o       = (const float*)d_in[3];
    const float* conv_k    = (const float*)d_in[4];
    const float* conv_v    = (const float*)d_in[5];
    float* out = (float*)d_out;

    float* qkv;
    __half *qh, *kh, *vh, *ah, *bh;
    cudaGetSymbolAddress((void**)&qkv, g_qkv);
    cudaGetSymbolAddress((void**)&qh,  g_qh);
    cudaGetSymbolAddress((void**)&kh,  g_kh);
    cudaGetSymbolAddress((void**)&vh,  g_vh);
    cudaGetSymbolAddress((void**)&ah,  g_ah);
    cudaGetSymbolAddress((void**)&bh,  g_bh);

    cudaFuncSetAttribute(gemm_mma, cudaFuncAttributeMaxDynamicSharedMemorySize,
                         GEMM_SMEM);
    cudaFuncSetAttribute(attn_mma, cudaFuncAttributeMaxDynamicSharedMemorySize,
                         ATTN_SMEM);

    // ---- 1) convert inputs (hidden + w_pack, one launch) ----
    conv_in_kernel<<<NB_HID + NB_WP, 256>>>(hidden, w_pack, ah, bh);

    // ---- 2) GEMM 1: qkv = hidden @ w_pack ----
    {
        dim3 g1(QKVF / 128, BSc / 128);
        gemm_mma<<<g1, 256, GEMM_SMEM>>>(ah, bh, qkv, BSc, QKVF, HIDc);
    }

    // ---- 3) fused prep: rope q / smooth+rope k / smooth v / w_o conv ----
    fused_prep_kernel<<<NB_Q + NB_K + NB_V + NB_WO, 256>>>(
        qkv, positions, conv_k, conv_v, w_o, qh, kh, vh, bh);

    // ---- 4) windowed attention (2 CTAs/SM); writes fp16 A for GEMM2 ----
    attn_mma<<<dim3(Sc / 64, Hc, Bc), 128, ATTN_SMEM>>>(qh, kh, vh, ah);

    // ---- 5) GEMM 2: out = attn @ w_o ----
    {
        dim3 g2(HIDc / 128, BSc / 128);
        gemm_mma<<<g2, 256, GEMM_SMEM>>>(ah, bh, out, BSc, HIDc, HIDc);
    }
}

// round 14
// speedup vs baseline: 1.9064x; 1.0247x over previous
#include <cuda_runtime.h>
#include <cuda_fp16.h>
#include <math.h>
#include <stdint.h>

// ---------------------------------------------------------------------------
// Problem constants
// ---------------------------------------------------------------------------
#define Bc    2
#define Sc    2048
#define HIDc  4096
#define Hc    32
#define KVc   8
#define Dc    128
#define Wc    512
#define BSc   (Bc * Sc)              // 4096
#define QKVF  ((Hc + 2 * KVc) * Dc)  // 6144

// global operand scale 2^10
#define SCF      1024.0f
#define INV_SC2  (1.0f / (SCF * SCF))
#define INV_SCF  (1.0f / SCF)
#define LOG2E    1.4426950408889634f

// ---------------------------------------------------------------------------
// Scratch (static device globals -- no allocation allowed)
// ---------------------------------------------------------------------------
__device__ __half g_qkvh[(size_t)BSc * QKVF];            // scaled fp16 qkv

__device__ __half g_qh[(size_t)BSc * Hc * Dc];           // roped Q [bs][h][d]
__device__ __half g_kh[(size_t)BSc * KVc * Dc];          // K [bs][kv][d]
__device__ __half g_vh[(size_t)BSc * KVc * Dc];          // V [bs][kv][d]

__device__ __half g_ah[(size_t)BSc * HIDc];              // GEMM A [M,K]
__device__ __half g_bh[(size_t)QKVF * HIDc];             // GEMM B [K,N]

// ---------------------------------------------------------------------------
// Helpers
// ---------------------------------------------------------------------------
__device__ __forceinline__ uint32_t smem_u32(const void* p) {
    uint32_t a;
    asm("{ .reg .u64 t; cvta.to.shared.u64 t, %1; cvt.u32.u64 %0, t; }"
        : "=r"(a) : "l"(p));
    return a;
}
__device__ __forceinline__ void cp16(uint32_t smem, const void* gmem) {
    asm volatile("cp.async.cg.shared.global [%0], [%1], 16;"
                 :: "r"(smem), "l"(gmem));
}
#define CP_COMMIT() asm volatile("cp.async.commit_group;" ::: "memory")
#define CP_WAIT0()  asm volatile("cp.async.wait_group 0;" ::: "memory")

__device__ __forceinline__ void ldsm_x4(uint32_t* r, uint32_t addr) {
    asm volatile("ldmatrix.sync.aligned.m8n8.x4.shared.b16 {%0,%1,%2,%3}, [%4];"
                 : "=r"(r[0]), "=r"(r[1]), "=r"(r[2]), "=r"(r[3]) : "r"(addr));
}
__device__ __forceinline__ void ldsm_x4_t(uint32_t* r, uint32_t addr) {
    asm volatile("ldmatrix.sync.aligned.m8n8.x4.trans.shared.b16 {%0,%1,%2,%3}, [%4];"
                 : "=r"(r[0]), "=r"(r[1]), "=r"(r[2]), "=r"(r[3]) : "r"(addr));
}

// fp16 HMMA m16n8k16, fp32 accumulate
__device__ __forceinline__ void mma16816(float* d, const uint32_t* a,
                                         const uint32_t* b) {
    asm volatile(
        "mma.sync.aligned.m16n8k16.row.col.f32.f16.f16.f32 "
        "{%0,%1,%2,%3}, {%4,%5,%6,%7}, {%8,%9}, {%0,%1,%2,%3};"
        : "+f"(d[0]), "+f"(d[1]), "+f"(d[2]), "+f"(d[3])
        : "r"(a[0]), "r"(a[1]), "r"(a[2]), "r"(a[3]),
          "r"(b[0]), "r"(b[1]));
}

__device__ __forceinline__ uint32_t packh2(float x, float y) {
    __half2 h(__float2half_rn(x), __float2half_rn(y));
    return *(uint32_t*)&h;
}

// ---------------------------------------------------------------------------
// fp16 HMMA GEMM, templated epilogue (fp16 scaled or fp32 true-value out)
// ---------------------------------------------------------------------------
#define GBK    64
#define AROW   144
#define BROW   272
#define MAT_A  (128 * AROW)
#define MAT_B  (64 * BROW)
#define STAGEB (MAT_A + MAT_B)
#define GEMM_SMEM (2 * STAGEB)

template <bool HOUT>
__global__ __launch_bounds__(256, 2)
void gemm_mma(const __half* __restrict__ Ah,
              const __half* __restrict__ Bh,
              void* __restrict__ Cv, int M, int N, int K)
{
    extern __shared__ char sm[];
    const uint32_t sb = smem_u32(sm);
    const int tid  = threadIdx.x;
    const int wid  = tid >> 5;
    const int lane = tid & 31;
    const int wm = wid & 3;
    const int wn = wid >> 2;
    const int g  = lane >> 2;
    const int tg = lane & 3;

    const int m0 = blockIdx.y * 128;
    const int n0 = blockIdx.x * 128;

    const uint32_t amrow = (lane & 7) + ((lane >> 3) & 1) * 8;
    const uint32_t acol  = (uint32_t)(lane >> 4) * 16;
    const uint32_t bkrow = (lane & 7) + ((lane >> 3) & 1) * 8;
    const uint32_t bncol = (uint32_t)(lane >> 4) * 16;

    auto load_stage = [&](int k0, int st) {
        const uint32_t base = sb + st * STAGEB;
#pragma unroll
        for (int hh = 0; hh < 4; hh++) {
            int unit = tid + hh * 256;
            int r = unit >> 3, u = unit & 7;
            const void* gp = Ah + (size_t)(m0 + r) * K + k0 + u * 8;
            cp16(base + r * AROW + u * 16, gp);
        }
#pragma unroll
        for (int hh = 0; hh < 4; hh++) {
            int unit = tid + hh * 256;
            int r = unit >> 4, u = unit & 15;
            const void* gp = Bh + (size_t)(k0 + r) * N + n0 + u * 8;
            cp16(base + MAT_A + r * BROW + u * 16, gp);
        }
    };

    float acc[2][8][4];
#pragma unroll
    for (int mt = 0; mt < 2; mt++)
#pragma unroll
        for (int nt = 0; nt < 8; nt++)
#pragma unroll
            for (int j = 0; j < 4; j++) acc[mt][nt][j] = 0.f;

    const int NIT = K / GBK;
    load_stage(0, 0);
    CP_COMMIT();

    for (int it = 0; it < NIT; it++) {
        CP_WAIT0();
        __syncthreads();
        const int st = it & 1;
        if (it + 1 < NIT) {
            load_stage((it + 1) * GBK, st ^ 1);
            CP_COMMIT();
        }

        const uint32_t ahb = sb + st * STAGEB;
        const uint32_t bhb = ahb + MAT_A;

#pragma unroll
        for (int ks = 0; ks < 4; ks++) {
            uint32_t ah[2][4];
#pragma unroll
            for (int mt = 0; mt < 2; mt++) {
                const uint32_t ar = ahb +
                    (uint32_t)((wm * 32 + mt * 16 + amrow) * AROW) +
                    (uint32_t)(ks * 32) + acol;
                ldsm_x4(ah[mt], ar);
            }
#pragma unroll
            for (int ntp = 0; ntp < 4; ntp++) {
                const uint32_t br = bhb +
                    (uint32_t)((ks * 16 + bkrow) * BROW) +
                    (uint32_t)((wn * 64 + ntp * 16) * 2) + bncol;
                uint32_t bh4[4];
                ldsm_x4_t(bh4, br);
#pragma unroll
                for (int mt = 0; mt < 2; mt++) {
                    mma16816(acc[mt][2 * ntp],     ah[mt], &bh4[0]);
                    mma16816(acc[mt][2 * ntp + 1], ah[mt], &bh4[2]);
                }
            }
        }
    }

#pragma unroll
    for (int mt = 0; mt < 2; mt++) {
        const int r0 = m0 + wm * 32 + mt * 16 + g;
#pragma unroll
        for (int nt = 0; nt < 8; nt++) {
            const int cc = n0 + wn * 64 + nt * 8 + tg * 2;
            if (HOUT) {
                // scaled fp16 out: value*SCF = acc * INV_SC2 * SCF = acc / SCF
                __half* cp = (__half*)Cv;
                *(uint32_t*)(cp + (size_t)r0 * N + cc) =
                    packh2(acc[mt][nt][0] * INV_SCF, acc[mt][nt][1] * INV_SCF);
                *(uint32_t*)(cp + (size_t)(r0 + 8) * N + cc) =
                    packh2(acc[mt][nt][2] * INV_SCF, acc[mt][nt][3] * INV_SCF);
            } else {
                float* cp = (float*)Cv;
                float2 w0 = make_float2(acc[mt][nt][0] * INV_SC2,
                                        acc[mt][nt][1] * INV_SC2);
                float2 w1 = make_float2(acc[mt][nt][2] * INV_SC2,
                                        acc[mt][nt][3] * INV_SC2);
                *(float2*)(cp + (size_t)r0 * N + cc)       = w0;
                *(float2*)(cp + (size_t)(r0 + 8) * N + cc) = w1;
            }
        }
    }
}

// ---------------------------------------------------------------------------
// Fused input conversion: hidden -> g_ah, w_pack -> g_bh
// ---------------------------------------------------------------------------
#define N4_HID  (BSc * HIDc / 4)
#define NB_HID  (N4_HID / 256)               // 16384
#define N4_WP   (HIDc * QKVF / 4)
#define NB_WP   (N4_WP / 256)                // 24576

__global__ void conv_in_kernel(const float* __restrict__ hidden,
                               const float* __restrict__ w_pack,
                               __half* __restrict__ Ah,
                               __half* __restrict__ Bh)
{
    int bid = blockIdx.x;
    if (bid < NB_HID) {
        int i = bid * 256 + threadIdx.x;
        float4 v = ((const float4*)hidden)[i];
        ((uint32_t*)Ah)[i * 2 + 0] = packh2(v.x * SCF, v.y * SCF);
        ((uint32_t*)Ah)[i * 2 + 1] = packh2(v.z * SCF, v.w * SCF);
    } else {
        int i = (bid - NB_HID) * 256 + threadIdx.x;
        float4 v = ((const float4*)w_pack)[i];
        ((uint32_t*)Bh)[i * 2 + 0] = packh2(v.x * SCF, v.y * SCF);
        ((uint32_t*)Bh)[i * 2 + 1] = packh2(v.z * SCF, v.w * SCF);
    }
}

// ---------------------------------------------------------------------------
// Fused prep from scaled-fp16 qkv: rope_q + smooth_k + smooth_v + w_o conv.
// All vectorized. Scale SCF passes through linear ops untouched.
// ---------------------------------------------------------------------------
#define NB_Q   (BSc * Hc * 16 / 256)         // 8192
#define NB_K   (BSc * KVc * 16 / 256)        // 2048
#define NB_V   (BSc * KVc * 16 / 256)        // 2048
#define N4_WO  (HIDc * HIDc / 4)
#define NB_WO  (N4_WO / 256)                 // 16384

__global__ void fused_prep_kernel(const __half* __restrict__ qkvh,
                                  const int* __restrict__ positions,
                                  const float* __restrict__ conv_k,
                                  const float* __restrict__ conv_v,
                                  const float* __restrict__ w_o,
                                  __half* __restrict__ Qh,
                                  __half* __restrict__ Kh,
                                  __half* __restrict__ Vh,
                                  __half* __restrict__ Bh)
{
    int bid = blockIdx.x;
    if (bid < NB_Q) {
        // ---- rope Q: 4 (i, i+64) pairs per thread ----
        int idx = bid * 256 + threadIdx.x;      // BSc*Hc*16
        int t  = idx & 15;
        int h  = (idx >> 4) & 31;
        int bs = idx >> 9;

        const __half* src = qkvh + (size_t)bs * QKVF + h * Dc;
        uint2 a = *(const uint2*)(src + t * 4);
        uint2 c = *(const uint2*)(src + t * 4 + 64);
        const __half* ah = (const __half*)&a;
        const __half* ch = (const __half*)&c;
        float pos = (float)positions[bs];

        uint32_t o1[2], o2[2];
#pragma unroll
        for (int j2 = 0; j2 < 2; j2++) {
            float y1[2], y2[2];
#pragma unroll
            for (int j = 0; j < 2; j++) {
                int i = t * 4 + j2 * 2 + j;
                float x1 = __half2float(ah[j2 * 2 + j]);
                float x2 = __half2float(ch[j2 * 2 + j]);
                float ang = pos * exp2f((float)i * -0.2076205059304601f);
                float sn, cs;
                sincosf(ang, &sn, &cs);
                y1[j] = x1 * cs - x2 * sn;
                y2[j] = x2 * cs + x1 * sn;
            }
            o1[j2] = packh2(y1[0], y1[1]);
            o2[j2] = packh2(y2[0], y2[1]);
        }
        size_t o = (size_t)bs * (Hc * Dc) + h * Dc;
        *(uint2*)(Qh + o + t * 4)      = make_uint2(o1[0], o1[1]);
        *(uint2*)(Qh + o + t * 4 + 64) = make_uint2(o2[0], o2[1]);
    } else if (bid < NB_Q + NB_K) {
        // ---- smooth + rope K ----
        int idx = (bid - NB_Q) * 256 + threadIdx.x;   // BSc*KVc*16
        int t  = idx & 15;
        int kv = (idx >> 4) & 7;
        int bs = idx >> 7;
        int s = bs & (Sc - 1);

        const __half* src = qkvh + (size_t)bs * QKVF + Hc * Dc + kv * Dc;
        uint2 a = *(const uint2*)(src + t * 4);
        uint2 c = *(const uint2*)(src + t * 4 + 64);
        uint2 pa = make_uint2(0, 0), pc = make_uint2(0, 0);
        if (s > 0) {
            pa = *(const uint2*)(src - QKVF + t * 4);
            pc = *(const uint2*)(src - QKVF + t * 4 + 64);
        }
        const __half* ah = (const __half*)&a;
        const __half* ch = (const __half*)&c;
        const __half* pah = (const __half*)&pa;
        const __half* pch = (const __half*)&pc;
        float f0 = conv_k[kv], f1 = conv_k[KVc + kv];
        float pos = (float)positions[bs];

        uint32_t o1[2], o2[2];
#pragma unroll
        for (int j2 = 0; j2 < 2; j2++) {
            float y1[2], y2[2];
#pragma unroll
            for (int j = 0; j < 2; j++) {
                int i = t * 4 + j2 * 2 + j;
                float x1 = __half2float(ah[j2 * 2 + j]) * f1 +
                           __half2float(pah[j2 * 2 + j]) * f0;
                float x2 = __half2float(ch[j2 * 2 + j]) * f1 +
                           __half2float(pch[j2 * 2 + j]) * f0;
                float ang = pos * exp2f((float)i * -0.2076205059304601f);
                float sn, cs;
                sincosf(ang, &sn, &cs);
                y1[j] = x1 * cs - x2 * sn;
                y2[j] = x2 * cs + x1 * sn;
            }
            o1[j2] = packh2(y1[0], y1[1]);
            o2[j2] = packh2(y2[0], y2[1]);
        }
        size_t o = ((size_t)bs * KVc + kv) * Dc;
        *(uint2*)(Kh + o + t * 4)      = make_uint2(o1[0], o1[1]);
        *(uint2*)(Kh + o + t * 4 + 64) = make_uint2(o2[0], o2[1]);
    } else if (bid < NB_Q + NB_K + NB_V) {
        // ---- smooth V: 8 elems per thread ----
        int idx = (bid - NB_Q - NB_K) * 256 + threadIdx.x;   // BSc*KVc*16
        int t  = idx & 15;
        int kv = (idx >> 4) & 7;
        int bs = idx >> 7;
        int s = bs & (Sc - 1);

        const __half* src = qkvh + (size_t)bs * QKVF + (Hc + KVc) * Dc + kv * Dc;
        uint4 cu = *(const uint4*)(src + t * 8);
        uint4 pu = make_uint4(0, 0, 0, 0);
        if (s > 0) pu = *(const uint4*)(src - QKVF + t * 8);
        const __half* chh = (const __half*)&cu;
        const __half* phh = (const __half*)&pu;
        float f0 = conv_v[kv], f1 = conv_v[KVc + kv];

        uint32_t ow[4];
#pragma unroll
        for (int j2 = 0; j2 < 4; j2++) {
            float v0 = __half2float(chh[j2 * 2])     * f1 +
                       __half2float(phh[j2 * 2])     * f0;
            float v1 = __half2float(chh[j2 * 2 + 1]) * f1 +
                       __half2float(phh[j2 * 2 + 1]) * f0;
            ow[j2] = packh2(v0, v1);
        }
        size_t o = ((size_t)bs * KVc + kv) * Dc + t * 8;
        *(uint4*)(Vh + o) = make_uint4(ow[0], ow[1], ow[2], ow[3]);
    } else {
        // ---- w_o conversion ----
        int i = (bid - NB_Q - NB_K - NB_V) * 256 + threadIdx.x;
        float4 v = ((const float4*)w_o)[i];
        ((uint32_t*)Bh)[i * 2 + 0] = packh2(v.x * SCF, v.y * SCF);
        ((uint32_t*)Bh)[i * 2 + 1] = packh2(v.z * SCF, v.w * SCF);
    }
}

// ---------------------------------------------------------------------------
// Register-resident windowed flash attention (unchanged from R13 passing)
// ---------------------------------------------------------------------------
#define RQK  272

#define A_QH   0
#define A_ST0  (A_QH + 64 * RQK)
#define KV_STAGE (2 * 64 * RQK)
#define ST_KH  0
#define ST_VH  (64 * RQK)
#define ATTN_SMEM (A_ST0 + 2 * KV_STAGE)            // 87040

__global__ __launch_bounds__(128, 2)
void attn_mma(const __half* __restrict__ Qh,
              const __half* __restrict__ Kh, const __half* __restrict__ Vh,
              __half* __restrict__ Oh)
{
    extern __shared__ char sm[];
    const uint32_t sb = smem_u32(sm);

    const int tid  = threadIdx.x;
    const int w    = tid >> 5;
    const int lane = tid & 31;
    const int g  = lane >> 2;
    const int tg = lane & 3;

    const int qt = blockIdx.x, h = blockIdx.y, b = blockIdx.z;
    const int q0 = qt * 64;
    const int kvh = h >> 2;
    const float scale_eff = 0.08838834764831845f * INV_SC2 * LOG2E;

    const uint32_t bmrow = (lane & 7) + (uint32_t)(lane >> 4) * 8;
    const uint32_t bcol  = ((lane >> 3) & 1) * 16;
    const uint32_t vkrow = (lane & 7) + ((lane >> 3) & 1) * 8;
    const uint32_t vncol = (uint32_t)(lane >> 4) * 16;

    {
        const size_t qbase = ((size_t)(b * Sc + q0) * Hc + h) * Dc;
#pragma unroll
        for (int hh = 0; hh < 8; hh++) {
            int idx = tid + hh * 128;
            int r = idx >> 4, u = idx & 15;
            const size_t go = qbase + (size_t)r * (Hc * Dc) + u * 8;
            cp16(sb + A_QH + r * RQK + u * 16, Qh + go);
        }
    }

    const size_t kvbase = ((size_t)b * Sc * KVc + kvh) * Dc;
    auto load_kv = [&](int kt, int st) {
        const int k0 = kt * 64;
        const uint32_t stb = sb + A_ST0 + st * KV_STAGE;
#pragma unroll
        for (int hh = 0; hh < 8; hh++) {
            int idx = tid + hh * 128;
            int r = idx >> 4, u = idx & 15;
            const size_t go = kvbase + (size_t)(k0 + r) * (KVc * Dc) + u * 8;
            cp16(stb + ST_KH + r * RQK + u * 16, Kh + go);
            cp16(stb + ST_VH + r * RQK + u * 16, Vh + go);
        }
    };

    float m0 = -1e30f, m1 = -1e30f, l0 = 0.f, l1 = 0.f;
    float oacc[16][4];
#pragma unroll
    for (int nt = 0; nt < 16; nt++)
#pragma unroll
        for (int j = 0; j < 4; j++) oacc[nt][j] = 0.f;

    const int qw_lo = q0 + w * 16;
    const int qw_hi = qw_lo + 15;
    const int qi0 = qw_lo + g;
    const int qi1 = qi0 + 8;

    int kt_lo = qt - 8; if (kt_lo < 0) kt_lo = 0;
    const int kt_hi = qt;

    load_kv(kt_lo, 0);
    CP_COMMIT();

    uint32_t qfh[8][4];

    for (int kt = kt_lo; kt <= kt_hi; kt++) {
        const int st = (kt - kt_lo) & 1;
        const int k0 = kt * 64;
        CP_WAIT0();
        __syncthreads();

        if (kt == kt_lo) {
            const uint32_t amrow = (lane & 7) + ((lane >> 3) & 1) * 8;
            const uint32_t acol  = (uint32_t)(lane >> 4) * 16;
#pragma unroll
            for (int ks = 0; ks < 8; ks++) {
                const uint32_t ar = (uint32_t)((w * 16 + amrow) * RQK) +
                                    (uint32_t)(ks * 32) + acol;
                ldsm_x4(qfh[ks], sb + A_QH + ar);
            }
        }

        if (kt < kt_hi) {
            load_kv(kt + 1, st ^ 1);
            CP_COMMIT();
        }

        if (k0 > qw_hi) continue;
        if (k0 + 575 <= qw_lo) continue;

        const uint32_t stb = sb + A_ST0 + st * KV_STAGE;
        const uint32_t khb = stb + ST_KH;
        const uint32_t vhb = stb + ST_VH;

        float sacc[8][4];
#pragma unroll
        for (int nt = 0; nt < 8; nt++)
#pragma unroll
            for (int j = 0; j < 4; j++) sacc[nt][j] = 0.f;

#pragma unroll
        for (int ks = 0; ks < 8; ks++) {
#pragma unroll
            for (int ntp = 0; ntp < 4; ntp++) {
                const uint32_t br = khb + (uint32_t)((ntp * 16 + bmrow) * RQK) +
                                    (uint32_t)(ks * 32) + bcol;
                uint32_t kh4[4];
                ldsm_x4(kh4, br);
                mma16816(sacc[2 * ntp],     qfh[ks], &kh4[0]);
                mma16816(sacc[2 * ntp + 1], qfh[ks], &kh4[2]);
            }
        }

        const bool fully_valid = (k0 + 63 <= qw_lo) && (k0 >= qw_hi - (Wc - 1));
        if (fully_valid) {
#pragma unroll
            for (int nt = 0; nt < 8; nt++)
#pragma unroll
                for (int j = 0; j < 4; j++) sacc[nt][j] *= scale_eff;
        } else {
#pragma unroll
            for (int nt = 0; nt < 8; nt++) {
                const int ki0 = k0 + nt * 8 + tg * 2, ki1 = ki0 + 1;
                bool m00 = (ki0 <= qi0) && (qi0 - ki0 < Wc);
                bool m01 = (ki1 <= qi0) && (qi0 - ki1 < Wc);
                bool m10 = (ki0 <= qi1) && (qi1 - ki0 < Wc);
                bool m11 = (ki1 <= qi1) && (qi1 - ki1 < Wc);
                sacc[nt][0] = m00 ? sacc[nt][0] * scale_eff : -1e30f;
                sacc[nt][1] = m01 ? sacc[nt][1] * scale_eff : -1e30f;
                sacc[nt][2] = m10 ? sacc[nt][2] * scale_eff : -1e30f;
                sacc[nt][3] = m11 ? sacc[nt][3] * scale_eff : -1e30f;
            }
        }

        float mx0 = -1e30f, mx1 = -1e30f;
#pragma unroll
        for (int nt = 0; nt < 8; nt++) {
            mx0 = fmaxf(mx0, fmaxf(sacc[nt][0], sacc[nt][1]));
            mx1 = fmaxf(mx1, fmaxf(sacc[nt][2], sacc[nt][3]));
        }
        mx0 = fmaxf(mx0, __shfl_xor_sync(0xffffffffu, mx0, 1));
        mx0 = fmaxf(mx0, __shfl_xor_sync(0xffffffffu, mx0, 2));
        mx1 = fmaxf(mx1, __shfl_xor_sync(0xffffffffu, mx1, 1));
        mx1 = fmaxf(mx1, __shfl_xor_sync(0xffffffffu, mx1, 2));

        const float mn0 = fmaxf(m0, mx0);
        const float mn1 = fmaxf(m1, mx1);
        const float f0 = exp2f(m0 - mn0);
        const float f1 = exp2f(m1 - mn1);
        m0 = mn0; m1 = mn1;

        float s0 = 0.f, s1 = 0.f;
#pragma unroll
        for (int nt = 0; nt < 8; nt++) {
            float p0 = (sacc[nt][0] > -1e29f) ? exp2f(sacc[nt][0] - mn0) : 0.f;
            float p1 = (sacc[nt][1] > -1e29f) ? exp2f(sacc[nt][1] - mn0) : 0.f;
            float p2 = (sacc[nt][2] > -1e29f) ? exp2f(sacc[nt][2] - mn1) : 0.f;
            float p3 = (sacc[nt][3] > -1e29f) ? exp2f(sacc[nt][3] - mn1) : 0.f;
            sacc[nt][0] = p0; sacc[nt][1] = p1; sacc[nt][2] = p2; sacc[nt][3] = p3;
            s0 += p0 + p1; s1 += p2 + p3;
        }
        s0 += __shfl_xor_sync(0xffffffffu, s0, 1);
        s0 += __shfl_xor_sync(0xffffffffu, s0, 2);
        s1 += __shfl_xor_sync(0xffffffffu, s1, 1);
        s1 += __shfl_xor_sync(0xffffffffu, s1, 2);
        l0 = l0 * f0 + s0;
        l1 = l1 * f1 + s1;

#pragma unroll
        for (int nt = 0; nt < 16; nt++) {
            oacc[nt][0] *= f0; oacc[nt][1] *= f0;
            oacc[nt][2] *= f1; oacc[nt][3] *= f1;
        }

#pragma unroll
        for (int ks = 0; ks < 4; ks++) {
            uint32_t aph[4];
            aph[0] = packh2(sacc[2 * ks][0] * SCF,     sacc[2 * ks][1] * SCF);
            aph[1] = packh2(sacc[2 * ks][2] * SCF,     sacc[2 * ks][3] * SCF);
            aph[2] = packh2(sacc[2 * ks + 1][0] * SCF, sacc[2 * ks + 1][1] * SCF);
            aph[3] = packh2(sacc[2 * ks + 1][2] * SCF, sacc[2 * ks + 1][3] * SCF);
#pragma unroll
            for (int ntp = 0; ntp < 8; ntp++) {
                const uint32_t br = vhb + (uint32_t)((ks * 16 + vkrow) * RQK) +
                                    (uint32_t)(ntp * 32) + vncol;
                uint32_t vh4[4];
                ldsm_x4_t(vh4, br);
                mma16816(oacc[2 * ntp],     aph, &vh4[0]);
                mma16816(oacc[2 * ntp + 1], aph, &vh4[2]);
            }
        }
    }

    {
        const float linv0 = (1.0f / l0) * (1.0f / SCF);
        const float linv1 = (1.0f / l1) * (1.0f / SCF);
        const size_t tok0 = (size_t)(b * Sc + qw_lo + g);
        const size_t tok1 = tok0 + 8;
#pragma unroll
        for (int nt = 0; nt < 16; nt++) {
            const int col = h * Dc + nt * 8 + tg * 2;
            ((uint32_t*)Oh)[(tok0 * HIDc + col) >> 1] =
                packh2(oacc[nt][0] * linv0, oacc[nt][1] * linv0);
            ((uint32_t*)Oh)[(tok1 * HIDc + col) >> 1] =
                packh2(oacc[nt][2] * linv1, oacc[nt][3] * linv1);
        }
    }
}

// ---------------------------------------------------------------------------
// Launch
// ---------------------------------------------------------------------------
extern "C" void kernel_launch(void* const* d_in, const int* in_sizes, int n_in,
                              void* d_out, int out_size)
{
    const float* hidden    = (const float*)d_in[0];
    const int*   positions = (const int*)d_in[1];
    const float* w_pack    = (const float*)d_in[2];
    const float* w_o       = (const float*)d_in[3];
    const float* conv_k    = (const float*)d_in[4];
    const float* conv_v    = (const float*)d_in[5];
    float* out = (float*)d_out;

    __half *qkvh, *qh, *kh, *vh, *ah, *bh;
    cudaGetSymbolAddress((void**)&qkvh, g_qkvh);
    cudaGetSymbolAddress((void**)&qh,  g_qh);
    cudaGetSymbolAddress((void**)&kh,  g_kh);
    cudaGetSymbolAddress((void**)&vh,  g_vh);
    cudaGetSymbolAddress((void**)&ah,  g_ah);
    cudaGetSymbolAddress((void**)&bh,  g_bh);

    cudaFuncSetAttribute(gemm_mma<true>,
                         cudaFuncAttributeMaxDynamicSharedMemorySize, GEMM_SMEM);
    cudaFuncSetAttribute(gemm_mma<false>,
                         cudaFuncAttributeMaxDynamicSharedMemorySize, GEMM_SMEM);
    cudaFuncSetAttribute(attn_mma,
                         cudaFuncAttributeMaxDynamicSharedMemorySize, ATTN_SMEM);

    // ---- 1) convert inputs (hidden + w_pack) ----
    conv_in_kernel<<<NB_HID + NB_WP, 256>>>(hidden, w_pack, ah, bh);

    // ---- 2) GEMM 1: qkvh (scaled fp16) = hidden @ w_pack ----
    {
        dim3 g1(QKVF / 128, BSc / 128);
        gemm_mma<true><<<g1, 256, GEMM_SMEM>>>(ah, bh, qkvh, BSc, QKVF, HIDc);
    }

    // ---- 3) fused prep (vectorized, fp16 qkv source) ----
    fused_prep_kernel<<<NB_Q + NB_K + NB_V + NB_WO, 256>>>(
        qkvh, positions, conv_k, conv_v, w_o, qh, kh, vh, bh);

    // ---- 4) windowed attention; writes fp16 A for GEMM2 ----
    attn_mma<<<dim3(Sc / 64, Hc, Bc), 128, ATTN_SMEM>>>(qh, kh, vh, ah);

    // ---- 5) GEMM 2: out (fp32) = attn @ w_o ----
    {
        dim3 g2(HIDc / 128, BSc / 128);
        gemm_mma<false><<<g2, 256, GEMM_SMEM>>>(ah, bh, out, BSc, HIDc, HIDc);
    }
}